// round 5
// baseline (speedup 1.0000x reference)
#include <cuda_runtime.h>
#include <cuda_bf16.h>
#include <cstdint>

#define DIMC 256
#define NPIX 4096
#define BATCH 16
#define HID 512
#define NH 8
#define DH 64

#define BK 32
#define PAD 4
#define LROW (BK + PAD)    // bf16 elems per smem row

// ---------------- scratch (device globals, no allocation) ----------------
__device__ float g_Gp[4 * BATCH * DIMC * DIMC];  // split-K partials of G
__device__ float g_G [BATCH * DIMC * DIMC];      // G_b = X X^T
__device__ float g_P [BATCH * HID * DIMC];       // P_b = Wk @ G_b
__device__ float g_C [BATCH * NH * DH * DH];     // C_bh = P_bh @ Wv_h^T
__device__ float g_M [BATCH * HID * DIMC];       // M[h*64+e][c] = (C^T Wq /8)
__device__ float g_A [BATCH * DIMC * DIMC];      // A_b = W_out @ M_b

// ---------------- helpers ----------------
__device__ __forceinline__ void split2(float v, __nv_bfloat16& h, __nv_bfloat16& l) {
    h = __float2bfloat16(v);
    l = __float2bfloat16(v - __bfloat162float(h));
}

__device__ __forceinline__ void mma16816(float c[4],
                                         uint32_t a0, uint32_t a1, uint32_t a2, uint32_t a3,
                                         uint32_t b0, uint32_t b1) {
    asm volatile(
        "mma.sync.aligned.m16n8k16.row.col.f32.bf16.bf16.f32 "
        "{%0,%1,%2,%3},{%4,%5,%6,%7},{%8,%9},{%0,%1,%2,%3};"
        : "+f"(c[0]), "+f"(c[1]), "+f"(c[2]), "+f"(c[3])
        : "r"(a0), "r"(a1), "r"(a2), "r"(a3), "r"(b0), "r"(b1));
}

// K-contiguous loader: tile(r,k) = src[r*ld + k0 + k], 128 rows x 32 k, fp32 -> hi/lo bf16
__device__ __forceinline__ void load_kc(const float* __restrict__ src, int ld, int rows,
                                        int k0, __nv_bfloat16* hi, __nv_bfloat16* lo, int tid) {
    #pragma unroll
    for (int i = 0; i < 4; ++i) {
        int idx = tid + i * 256;          // 0..1023
        int r = idx >> 3, q = idx & 7;
        int rs = r < rows ? r : 0;
        float4 v = *(const float4*)(src + (size_t)rs * ld + k0 + q * 4);
        int o = r * LROW + q * 4;
        split2(v.x, hi[o+0], lo[o+0]);
        split2(v.y, hi[o+1], lo[o+1]);
        split2(v.z, hi[o+2], lo[o+2]);
        split2(v.w, hi[o+3], lo[o+3]);
    }
}

// MN-contiguous loader: tile(r,k) = src[(k0+k)*ld + r]
__device__ __forceinline__ void load_mn(const float* __restrict__ src, int ld, int rows,
                                        int k0, __nv_bfloat16* hi, __nv_bfloat16* lo, int tid) {
    #pragma unroll
    for (int i = 0; i < 16; ++i) {
        int idx = tid + i * 256;          // 0..4095
        int r = idx & 127, k = idx >> 7;
        int rs = r < rows ? r : 0;
        float v = src[(size_t)(k0 + k) * ld + rs];
        int o = r * LROW + k;
        split2(v, hi[o], lo[o]);
    }
}

// ---------------- modes ----------------
#define MODE_SYRK  0
#define MODE_S1    1
#define MODE_S2    2
#define MODE_S3    3
#define MODE_S4    4
#define MODE_FINAL 5

__global__ void __launch_bounds__(256)
mma_kernel(int mode, const float* __restrict__ x, const float* __restrict__ w_qkv,
           const float* __restrict__ w_out, const float* __restrict__ b_out,
           float* __restrict__ out)
{
    __shared__ __nv_bfloat16 As_hi[128 * LROW];
    __shared__ __nv_bfloat16 As_lo[128 * LROW];
    __shared__ __nv_bfloat16 Bs_hi[128 * LROW];
    __shared__ __nv_bfloat16 Bs_lo[128 * LROW];

    const int tid = threadIdx.x;
    const int lane = tid & 31, wid = tid >> 5;
    const int wm = wid >> 2, wn = wid & 3;   // 2 x 4 warp grid
    const int m0 = wm * 64, n0 = wn * 32;
    const int bx = blockIdx.x;

    // ---- decode job ----
    const float *A, *B;
    int lda, ldb, K, Ar, Br;
    bool a_mn = false, b_mn = false;
    int orows = 128, ocols = 128, ldo;
    float esc = 1.0f;
    const float* bias = nullptr;
    float* eo;
    float* em = nullptr;   // mirror (SYRK off-diag)

    if (mode == MODE_SYRK) {
        int p = bx % 3, ks = (bx / 3) & 3, b = bx / 12;
        int ti = (p == 2) ? 1 : 0;
        int tj = (p == 0) ? 0 : 1;
        A = x + ((size_t)b * DIMC + ti * 128) * NPIX + ks * 1024;
        B = x + ((size_t)b * DIMC + tj * 128) * NPIX + ks * 1024;
        lda = NPIX; ldb = NPIX; K = 1024; Ar = 128; Br = 128;
        ldo = DIMC;
        float* Gp = g_Gp + ((size_t)ks * BATCH + b) * DIMC * DIMC;
        eo = Gp + (size_t)ti * 128 * DIMC + tj * 128;
        if (ti != tj) em = Gp + (size_t)tj * 128 * DIMC + ti * 128;
    } else if (mode == MODE_S1) {
        int nt = bx & 1, mt = (bx >> 1) & 3, b = bx >> 3;
        A = w_qkv + (size_t)(HID + mt * 128) * DIMC;
        B = g_G + (size_t)b * DIMC * DIMC + (size_t)nt * 128 * DIMC;  // G symmetric
        lda = DIMC; ldb = DIMC; K = DIMC; Ar = 128; Br = 128; ldo = DIMC;
        eo = g_P + (size_t)b * HID * DIMC + (size_t)mt * 128 * DIMC + nt * 128;
    } else if (mode == MODE_S2) {
        int h = bx & 7, b = bx >> 3;
        A = g_P + (size_t)b * HID * DIMC + (size_t)h * 64 * DIMC;
        B = w_qkv + (size_t)(2 * HID + h * 64) * DIMC;
        lda = DIMC; ldb = DIMC; K = DIMC; Ar = 64; Br = 64;
        orows = 64; ocols = 64; ldo = 64;
        eo = g_C + (size_t)bx * DH * DH;
    } else if (mode == MODE_S3) {
        int nt = bx & 1, bh = bx >> 1, h = bh & 7, b = bh >> 3;
        A = g_C + (size_t)bh * DH * DH;                 // A(e,d)=C[d*64+e]
        B = w_qkv + (size_t)h * 64 * DIMC + nt * 128;   // B(c,d)=wq[(h64+d)*256+c]
        a_mn = true; b_mn = true;
        lda = 64; ldb = DIMC; K = DH; Ar = 64; Br = 128;
        orows = 64; ocols = 128; ldo = DIMC; esc = 0.125f;
        eo = g_M + (size_t)b * HID * DIMC + (size_t)h * 64 * DIMC + nt * 128;
    } else if (mode == MODE_S4) {
        int nt = bx & 1, mt = (bx >> 1) & 1, b = bx >> 2;
        A = w_out + (size_t)mt * 128 * HID;
        B = g_M + (size_t)b * HID * DIMC + nt * 128;    // B(c,j)=M[j][c]
        b_mn = true;
        lda = HID; ldb = DIMC; K = HID; Ar = 128; Br = 128; ldo = DIMC;
        eo = g_A + (size_t)b * DIMC * DIMC + (size_t)mt * 128 * DIMC + nt * 128;
    } else {  // MODE_FINAL
        int nt = bx & 31, mt = (bx >> 5) & 1, b = bx >> 6;
        A = g_A + (size_t)b * DIMC * DIMC + (size_t)mt * 128 * DIMC;
        B = x + (size_t)b * DIMC * NPIX + nt * 128;     // B(pix,c)=x[c][pix]
        b_mn = true;
        lda = DIMC; ldb = NPIX; K = DIMC; Ar = 128; Br = 128; ldo = NPIX;
        bias = b_out + mt * 128;
        eo = out + (size_t)b * DIMC * NPIX + (size_t)mt * 128 * NPIX + nt * 128;
    }

    float acc[4][4][4];
    #pragma unroll
    for (int a = 0; a < 4; ++a)
        #pragma unroll
        for (int b2 = 0; b2 < 4; ++b2)
            #pragma unroll
            for (int c = 0; c < 4; ++c) acc[a][b2][c] = 0.0f;

    // ---- main loop ----
    const int nch = K >> 5;
    for (int ch = 0; ch < nch; ++ch) {
        int k0 = ch * BK;
        if (a_mn) load_mn(A, lda, Ar, k0, As_hi, As_lo, tid);
        else      load_kc(A, lda, Ar, k0, As_hi, As_lo, tid);
        if (b_mn) load_mn(B, ldb, Br, k0, Bs_hi, Bs_lo, tid);
        else      load_kc(B, ldb, Br, k0, Bs_hi, Bs_lo, tid);
        __syncthreads();

        #pragma unroll
        for (int s = 0; s < 2; ++s) {
            const int kb = s * 16 + (lane & 3) * 2;
            const int ar = lane >> 2;
            uint32_t ah[4][4], al[4][4];
            #pragma unroll
            for (int mi = 0; mi < 4; ++mi) {
                int r = m0 + mi * 16 + ar;
                ah[mi][0] = *(const uint32_t*)&As_hi[r * LROW + kb];
                ah[mi][1] = *(const uint32_t*)&As_hi[(r + 8) * LROW + kb];
                ah[mi][2] = *(const uint32_t*)&As_hi[r * LROW + kb + 8];
                ah[mi][3] = *(const uint32_t*)&As_hi[(r + 8) * LROW + kb + 8];
                al[mi][0] = *(const uint32_t*)&As_lo[r * LROW + kb];
                al[mi][1] = *(const uint32_t*)&As_lo[(r + 8) * LROW + kb];
                al[mi][2] = *(const uint32_t*)&As_lo[r * LROW + kb + 8];
                al[mi][3] = *(const uint32_t*)&As_lo[(r + 8) * LROW + kb + 8];
            }
            #pragma unroll
            for (int ni = 0; ni < 4; ++ni) {
                int n = n0 + ni * 8 + ar;
                uint32_t bh0 = *(const uint32_t*)&Bs_hi[n * LROW + kb];
                uint32_t bh1 = *(const uint32_t*)&Bs_hi[n * LROW + kb + 8];
                uint32_t bl0 = *(const uint32_t*)&Bs_lo[n * LROW + kb];
                uint32_t bl1 = *(const uint32_t*)&Bs_lo[n * LROW + kb + 8];
                #pragma unroll
                for (int mi = 0; mi < 4; ++mi) {
                    mma16816(acc[mi][ni], ah[mi][0], ah[mi][1], ah[mi][2], ah[mi][3], bh0, bh1);
                    mma16816(acc[mi][ni], ah[mi][0], ah[mi][1], ah[mi][2], ah[mi][3], bl0, bl1);
                    mma16816(acc[mi][ni], al[mi][0], al[mi][1], al[mi][2], al[mi][3], bh0, bh1);
                }
            }
        }
        __syncthreads();
    }

    // ---- epilogue ----
    const int gr = lane >> 2, gc = (lane & 3) * 2;
    #pragma unroll
    for (int mi = 0; mi < 4; ++mi) {
        #pragma unroll
        for (int ni = 0; ni < 4; ++ni) {
            int r = m0 + mi * 16 + gr;
            int c = n0 + ni * 8 + gc;
            if (r >= orows || c >= ocols) continue;
            float v0 = acc[mi][ni][0] * esc;
            float v1 = acc[mi][ni][1] * esc;
            float v2 = acc[mi][ni][2] * esc;
            float v3 = acc[mi][ni][3] * esc;
            if (bias) {
                float bl = bias[r], bh = bias[r + 8];
                v0 += bl; v1 += bl; v2 += bh; v3 += bh;
            }
            float2 p0 = {v0, v1}, p1 = {v2, v3};
            *(float2*)&eo[(size_t)r * ldo + c] = p0;
            *(float2*)&eo[(size_t)(r + 8) * ldo + c] = p1;
            if (em) {
                em[(size_t)c * ldo + r] = v0;
                em[(size_t)(c + 1) * ldo + r] = v1;
                em[(size_t)c * ldo + r + 8] = v2;
                em[(size_t)(c + 1) * ldo + r + 8] = v3;
            }
        }
    }
}

// ---------------- reduce split-K partials ----------------
__global__ void reduce_g() {
    int idx = blockIdx.x * 256 + threadIdx.x;            // 262144 float4s
    const size_t S = (size_t)BATCH * DIMC * DIMC / 4;
    const float4* p = (const float4*)g_Gp;
    float4 a = p[idx], b = p[idx + S], c = p[idx + 2 * S], d = p[idx + 3 * S];
    float4 r;
    r.x = a.x + b.x + c.x + d.x;
    r.y = a.y + b.y + c.y + d.y;
    r.z = a.z + b.z + c.z + d.z;
    r.w = a.w + b.w + c.w + d.w;
    ((float4*)g_G)[idx] = r;
}

// ---------------- launch ----------------
extern "C" void kernel_launch(void* const* d_in, const int* in_sizes, int n_in,
                              void* d_out, int out_size)
{
    const float* x     = (const float*)d_in[0];
    const float* w_qkv = (const float*)d_in[1];
    const float* w_out = (const float*)d_in[2];
    const float* b_out = (const float*)d_in[3];
    float* out = (float*)d_out;

    mma_kernel<<<192,  256>>>(MODE_SYRK,  x, w_qkv, w_out, b_out, out);
    reduce_g  <<<1024, 256>>>();
    mma_kernel<<<128,  256>>>(MODE_S1,    x, w_qkv, w_out, b_out, out);
    mma_kernel<<<128,  256>>>(MODE_S2,    x, w_qkv, w_out, b_out, out);
    mma_kernel<<<256,  256>>>(MODE_S3,    x, w_qkv, w_out, b_out, out);
    mma_kernel<<<64,   256>>>(MODE_S4,    x, w_qkv, w_out, b_out, out);
    mma_kernel<<<1024, 256>>>(MODE_FINAL, x, w_qkv, w_out, b_out, out);
}

// round 6
// speedup vs baseline: 1.5060x; 1.5060x over previous
#include <cuda_runtime.h>
#include <cuda_bf16.h>
#include <cstdint>

typedef __nv_bfloat16 bf16;

#define DIMC 256
#define NPIX 4096
#define BATCH 16
#define HID 512
#define NH 8
#define DH 64
#define KS 8                  // SYRK split-K slices

#define BK 32
#define LROW 40               // 32 + 8 pad bf16 (80B row, 16B-aligned, odd bank stride)
#define TILEB (128 * LROW * 2)
#define STAGEB (4 * TILEB)
#define SMEMB (2 * STAGEB)    // 81920 B

// ---------------- scratch (device globals) ----------------
__device__ float g_Gp[KS * BATCH * DIMC * DIMC];
__device__ bf16 g_Xhi [BATCH * DIMC * NPIX];
__device__ bf16 g_Xlo [BATCH * DIMC * NPIX];
__device__ bf16 g_XThi[BATCH * NPIX * DIMC];
__device__ bf16 g_XTlo[BATCH * NPIX * DIMC];
__device__ bf16 g_Ghi [BATCH * DIMC * DIMC];
__device__ bf16 g_Glo [BATCH * DIMC * DIMC];
__device__ bf16 g_Phi [BATCH * HID * DIMC];
__device__ bf16 g_Plo [BATCH * HID * DIMC];
__device__ bf16 g_CThi[BATCH * NH * DH * DH];
__device__ bf16 g_CTlo[BATCH * NH * DH * DH];
__device__ bf16 g_MThi[BATCH * DIMC * HID];
__device__ bf16 g_MTlo[BATCH * DIMC * HID];
__device__ bf16 g_Ahi [BATCH * DIMC * DIMC];
__device__ bf16 g_Alo [BATCH * DIMC * DIMC];
__device__ bf16 g_Wh  [3 * HID * DIMC];
__device__ bf16 g_Wl  [3 * HID * DIMC];
__device__ bf16 g_WOh [DIMC * HID];
__device__ bf16 g_WOl [DIMC * HID];
__device__ bf16 g_WqTh[NH * DIMC * DH];
__device__ bf16 g_WqTl[NH * DIMC * DH];

// ---------------- helpers ----------------
__device__ __forceinline__ void split2(float v, bf16& h, bf16& l) {
    h = __float2bfloat16(v);
    l = __float2bfloat16(v - __bfloat162float(h));
}
__device__ __forceinline__ uint32_t smem_u32(const void* p) {
    uint32_t a;
    asm("{ .reg .u64 t; cvta.to.shared.u64 t, %1; cvt.u32.u64 %0, t; }" : "=r"(a) : "l"(p));
    return a;
}
__device__ __forceinline__ void cp16(uint32_t dst, const bf16* src) {
    asm volatile("cp.async.cg.shared.global [%0], [%1], 16;" :: "r"(dst), "l"(src));
}
#define CP_COMMIT() asm volatile("cp.async.commit_group;" ::: "memory")
#define CP_WAIT1()  asm volatile("cp.async.wait_group 1;" ::: "memory")
#define CP_WAIT0()  asm volatile("cp.async.wait_group 0;" ::: "memory")

__device__ __forceinline__ void mma16816(float c[4],
                                         uint32_t a0, uint32_t a1, uint32_t a2, uint32_t a3,
                                         uint32_t b0, uint32_t b1) {
    asm volatile(
        "mma.sync.aligned.m16n8k16.row.col.f32.bf16.bf16.f32 "
        "{%0,%1,%2,%3},{%4,%5,%6,%7},{%8,%9},{%0,%1,%2,%3};"
        : "+f"(c[0]), "+f"(c[1]), "+f"(c[2]), "+f"(c[3])
        : "r"(a0), "r"(a1), "r"(a2), "r"(a3), "r"(b0), "r"(b1));
}

// ---------------- transforms ----------------
__global__ void transform_x(const float* __restrict__ x) {
    __shared__ float tile[32][33];
    int b = blockIdx.z, c0 = blockIdx.y * 32, n0 = blockIdx.x * 32;
    int tx = threadIdx.x, ty = threadIdx.y;   // 32 x 8
    const float* xb = x + (size_t)b * DIMC * NPIX;
    #pragma unroll
    for (int i = 0; i < 4; ++i) {
        int c = c0 + ty + i * 8, n = n0 + tx;
        float v = xb[(size_t)c * NPIX + n];
        tile[ty + i * 8][tx] = v;
        size_t o = (size_t)b * DIMC * NPIX + (size_t)c * NPIX + n;
        split2(v, g_Xhi[o], g_Xlo[o]);
    }
    __syncthreads();
    #pragma unroll
    for (int i = 0; i < 4; ++i) {
        int n = n0 + ty + i * 8, c = c0 + tx;
        float v = tile[tx][ty + i * 8];
        size_t o = (size_t)b * NPIX * DIMC + (size_t)n * DIMC + c;
        split2(v, g_XThi[o], g_XTlo[o]);
    }
}

__global__ void wsplit(const float* __restrict__ w_qkv, const float* __restrict__ w_out) {
    int idx = blockIdx.x * 256 + threadIdx.x;
    if (idx < 3 * HID * DIMC) split2(w_qkv[idx], g_Wh[idx], g_Wl[idx]);
    if (idx < DIMC * HID)     split2(w_out[idx], g_WOh[idx], g_WOl[idx]);
    if (idx < NH * DIMC * DH) {
        int d = idx & 63, c = (idx >> 6) & 255, h = idx >> 14;
        float v = 0.125f * w_qkv[(size_t)(h * 64 + d) * DIMC + c];
        split2(v, g_WqTh[idx], g_WqTl[idx]);
    }
}

__global__ void reduce_g() {
    int idx = blockIdx.x * 256 + threadIdx.x;          // 1,048,576
    const int S = BATCH * DIMC * DIMC;
    float v = 0.0f;
    #pragma unroll
    for (int s = 0; s < KS; ++s) v += g_Gp[(size_t)s * S + idx];
    split2(v, g_Ghi[idx], g_Glo[idx]);
}

// ---------------- modes ----------------
#define MODE_SYRK  0
#define MODE_S1    1
#define MODE_S2    2
#define MODE_S3    3
#define MODE_S4    4
#define MODE_FINAL 5

#define EP_F32    0
#define EP_BIAS   1
#define EP_HILO   2
#define EP_HILO_T 3

__global__ void __launch_bounds__(512)
mma_kernel(int mode, const float* __restrict__ b_out, float* __restrict__ out)
{
    extern __shared__ char sm[];
    const int tid = threadIdx.x;
    const int lane = tid & 31, wid = tid >> 5;
    const int m0 = (wid >> 2) * 32, n0 = (wid & 3) * 32;   // 4x4 warps, 32x32 tiles
    const int bx = blockIdx.x;

    // ---- decode job ----
    const bf16 *Ahp, *Alp, *Bhp, *Blp;
    int lda, ldb, K, Ar, Br;
    int ep, orows = 128, ocols = 128, ldo;
    const float* bias = nullptr;
    float* eo32 = nullptr;
    float* em = nullptr;
    bf16 *eoh = nullptr, *eol = nullptr;

    if (mode == MODE_SYRK) {
        int p = bx % 3, ks = (bx / 3) & (KS - 1), b = bx / (3 * KS);
        int ti = (p == 2) ? 1 : 0;
        int tj = (p == 0) ? 0 : 1;
        size_t ao = ((size_t)b * DIMC + ti * 128) * NPIX + (size_t)ks * (NPIX / KS);
        size_t bo = ((size_t)b * DIMC + tj * 128) * NPIX + (size_t)ks * (NPIX / KS);
        Ahp = g_Xhi + ao; Alp = g_Xlo + ao; Bhp = g_Xhi + bo; Blp = g_Xlo + bo;
        lda = NPIX; ldb = NPIX; K = NPIX / KS; Ar = 128; Br = 128;
        ep = EP_F32; ldo = DIMC;
        float* Gp = g_Gp + ((size_t)ks * BATCH + b) * DIMC * DIMC;
        eo32 = Gp + (size_t)ti * 128 * DIMC + tj * 128;
        if (ti != tj) em = Gp + (size_t)tj * 128 * DIMC + ti * 128;
    } else if (mode == MODE_S1) {
        int nt = bx & 1, mt = (bx >> 1) & 3, b = bx >> 3;
        size_t ao = (size_t)(HID + mt * 128) * DIMC;
        size_t bo = (size_t)b * DIMC * DIMC + (size_t)nt * 128 * DIMC;   // G symmetric
        Ahp = g_Wh + ao; Alp = g_Wl + ao; Bhp = g_Ghi + bo; Blp = g_Glo + bo;
        lda = DIMC; ldb = DIMC; K = DIMC; Ar = 128; Br = 128;
        ep = EP_HILO; ldo = DIMC;
        size_t oo = (size_t)b * HID * DIMC + (size_t)mt * 128 * DIMC + nt * 128;
        eoh = g_Phi + oo; eol = g_Plo + oo;
    } else if (mode == MODE_S2) {
        int h = bx & 7, b = bx >> 3;
        size_t ao = (size_t)b * HID * DIMC + (size_t)h * 64 * DIMC;
        size_t bo = (size_t)(2 * HID + h * 64) * DIMC;
        Ahp = g_Phi + ao; Alp = g_Plo + ao; Bhp = g_Wh + bo; Blp = g_Wl + bo;
        lda = DIMC; ldb = DIMC; K = DIMC; Ar = 64; Br = 64;
        ep = EP_HILO_T; orows = 64; ocols = 64; ldo = 64;
        size_t oo = (size_t)bx * DH * DH;
        eoh = g_CThi + oo; eol = g_CTlo + oo;
    } else if (mode == MODE_S3) {
        int nt = bx & 1, bh = bx >> 1, h = bh & 7, b = bh >> 3;
        size_t ao = (size_t)bh * DH * DH;
        size_t bo = (size_t)h * DIMC * DH + (size_t)nt * 128 * DH;
        Ahp = g_CThi + ao; Alp = g_CTlo + ao; Bhp = g_WqTh + bo; Blp = g_WqTl + bo;
        lda = DH; ldb = DH; K = DH; Ar = 64; Br = 128;
        ep = EP_HILO_T; orows = 64; ocols = 128; ldo = HID;
        size_t oo = (size_t)b * DIMC * HID + (size_t)nt * 128 * HID + h * 64;
        eoh = g_MThi + oo; eol = g_MTlo + oo;
    } else if (mode == MODE_S4) {
        int nt = bx & 1, mt = (bx >> 1) & 1, b = bx >> 2;
        size_t ao = (size_t)mt * 128 * HID;
        size_t bo = (size_t)b * DIMC * HID + (size_t)nt * 128 * HID;
        Ahp = g_WOh + ao; Alp = g_WOl + ao; Bhp = g_MThi + bo; Blp = g_MTlo + bo;
        lda = HID; ldb = HID; K = HID; Ar = 128; Br = 128;
        ep = EP_HILO; ldo = DIMC;
        size_t oo = (size_t)b * DIMC * DIMC + (size_t)mt * 128 * DIMC + nt * 128;
        eoh = g_Ahi + oo; eol = g_Alo + oo;
    } else {  // MODE_FINAL
        int nt = bx & 31, mt = (bx >> 5) & 1, b = bx >> 6;
        size_t ao = (size_t)b * DIMC * DIMC + (size_t)mt * 128 * DIMC;
        size_t bo = (size_t)b * NPIX * DIMC + (size_t)nt * 128 * DIMC;
        Ahp = g_Ahi + ao; Alp = g_Alo + ao; Bhp = g_XThi + bo; Blp = g_XTlo + bo;
        lda = DIMC; ldb = DIMC; K = DIMC; Ar = 128; Br = 128;
        ep = EP_BIAS; ldo = NPIX;
        bias = b_out + mt * 128;
        eo32 = out + (size_t)b * DIMC * NPIX + (size_t)mt * 128 * NPIX + nt * 128;
    }

    // ---- cp.async loader setup ----
    const int lrow = tid >> 2, lq = tid & 3;            // 128 rows x 4 chunks of 8 bf16
    const int ra = lrow < Ar ? lrow : 0;
    const int rb = lrow < Br ? lrow : 0;
    const uint32_t sbase = smem_u32(sm);
    const uint32_t doff = (uint32_t)(lrow * LROW + lq * 8) * 2;

    auto issue = [&](int c) {
        uint32_t stg = sbase + (uint32_t)(c & 1) * STAGEB + doff;
        int k0 = c * BK + lq * 8;
        cp16(stg,             Ahp + (size_t)ra * lda + k0);
        cp16(stg + TILEB,     Alp + (size_t)ra * lda + k0);
        cp16(stg + 2 * TILEB, Bhp + (size_t)rb * ldb + k0);
        cp16(stg + 3 * TILEB, Blp + (size_t)rb * ldb + k0);
    };

    float acc[2][4][4];
    #pragma unroll
    for (int a = 0; a < 2; ++a)
        #pragma unroll
        for (int b2 = 0; b2 < 4; ++b2)
            #pragma unroll
            for (int c = 0; c < 4; ++c) acc[a][b2][c] = 0.0f;

    const int nch = K >> 5;                   // >= 2 for all modes
    issue(0); CP_COMMIT();
    issue(1); CP_COMMIT();
    CP_WAIT1();
    __syncthreads();

    for (int c = 0; c < nch; ++c) {
        const char* stp = sm + (c & 1) * STAGEB;
        const bf16* sAh = (const bf16*)(stp);
        const bf16* sAl = (const bf16*)(stp + TILEB);
        const bf16* sBh = (const bf16*)(stp + 2 * TILEB);
        const bf16* sBl = (const bf16*)(stp + 3 * TILEB);

        #pragma unroll
        for (int s = 0; s < 2; ++s) {
            const int kb = s * 16 + (lane & 3) * 2;
            const int ar = lane >> 2;
            uint32_t ah[2][4], al[2][4];
            #pragma unroll
            for (int mi = 0; mi < 2; ++mi) {
                int r = m0 + mi * 16 + ar;
                ah[mi][0] = *(const uint32_t*)&sAh[r * LROW + kb];
                ah[mi][1] = *(const uint32_t*)&sAh[(r + 8) * LROW + kb];
                ah[mi][2] = *(const uint32_t*)&sAh[r * LROW + kb + 8];
                ah[mi][3] = *(const uint32_t*)&sAh[(r + 8) * LROW + kb + 8];
                al[mi][0] = *(const uint32_t*)&sAl[r * LROW + kb];
                al[mi][1] = *(const uint32_t*)&sAl[(r + 8) * LROW + kb];
                al[mi][2] = *(const uint32_t*)&sAl[r * LROW + kb + 8];
                al[mi][3] = *(const uint32_t*)&sAl[(r + 8) * LROW + kb + 8];
            }
            #pragma unroll
            for (int ni = 0; ni < 4; ++ni) {
                int n = n0 + ni * 8 + ar;
                uint32_t bh0 = *(const uint32_t*)&sBh[n * LROW + kb];
                uint32_t bh1 = *(const uint32_t*)&sBh[n * LROW + kb + 8];
                uint32_t bl0 = *(const uint32_t*)&sBl[n * LROW + kb];
                uint32_t bl1 = *(const uint32_t*)&sBl[n * LROW + kb + 8];
                #pragma unroll
                for (int mi = 0; mi < 2; ++mi) {
                    mma16816(acc[mi][ni], ah[mi][0], ah[mi][1], ah[mi][2], ah[mi][3], bh0, bh1);
                    mma16816(acc[mi][ni], ah[mi][0], ah[mi][1], ah[mi][2], ah[mi][3], bl0, bl1);
                    mma16816(acc[mi][ni], al[mi][0], al[mi][1], al[mi][2], al[mi][3], bh0, bh1);
                }
            }
        }
        __syncthreads();                      // all warps done reading stage (c&1)
        if (c + 2 < nch) {
            issue(c + 2); CP_COMMIT(); CP_WAIT1();
        } else {
            CP_COMMIT(); CP_WAIT0();
        }
        __syncthreads();                      // next stage visible to all
    }

    // ---- epilogue ----
    const int gr = lane >> 2, gc = (lane & 3) * 2;
    #pragma unroll
    for (int mi = 0; mi < 2; ++mi) {
        #pragma unroll
        for (int ni = 0; ni < 4; ++ni) {
            int r = m0 + mi * 16 + gr;
            int c = n0 + ni * 8 + gc;
            if (r >= orows || c >= ocols) continue;
            float v0 = acc[mi][ni][0], v1 = acc[mi][ni][1];
            float v2 = acc[mi][ni][2], v3 = acc[mi][ni][3];
            if (ep == EP_BIAS) {
                float bl = bias[r], bh2 = bias[r + 8];
                v0 += bl; v1 += bl; v2 += bh2; v3 += bh2;
            }
            if (ep == EP_F32 || ep == EP_BIAS) {
                float2 p0 = {v0, v1}, p1 = {v2, v3};
                *(float2*)&eo32[(size_t)r * ldo + c] = p0;
                *(float2*)&eo32[(size_t)(r + 8) * ldo + c] = p1;
                if (em) {
                    em[(size_t)c * ldo + r] = v0;
                    em[(size_t)(c + 1) * ldo + r] = v1;
                    em[(size_t)c * ldo + r + 8] = v2;
                    em[(size_t)(c + 1) * ldo + r + 8] = v3;
                }
            } else if (ep == EP_HILO) {
                bf16 h0, l0, h1, l1, h2, l2, h3, l3;
                split2(v0, h0, l0); split2(v1, h1, l1);
                split2(v2, h2, l2); split2(v3, h3, l3);
                __nv_bfloat162 ph0 = {h0, h1}, pl0 = {l0, l1};
                __nv_bfloat162 ph1 = {h2, h3}, pl1 = {l2, l3};
                *(__nv_bfloat162*)&eoh[(size_t)r * ldo + c] = ph0;
                *(__nv_bfloat162*)&eol[(size_t)r * ldo + c] = pl0;
                *(__nv_bfloat162*)&eoh[(size_t)(r + 8) * ldo + c] = ph1;
                *(__nv_bfloat162*)&eol[(size_t)(r + 8) * ldo + c] = pl1;
            } else {   // EP_HILO_T : store transposed [col][row]
                bf16 h, l;
                split2(v0, h, l); eoh[(size_t)c * ldo + r] = h;       eol[(size_t)c * ldo + r] = l;
                split2(v1, h, l); eoh[(size_t)(c + 1) * ldo + r] = h; eol[(size_t)(c + 1) * ldo + r] = l;
                split2(v2, h, l); eoh[(size_t)c * ldo + r + 8] = h;   eol[(size_t)c * ldo + r + 8] = l;
                split2(v3, h, l); eoh[(size_t)(c + 1) * ldo + r + 8] = h; eol[(size_t)(c + 1) * ldo + r + 8] = l;
            }
        }
    }
}

// ---------------- launch ----------------
extern "C" void kernel_launch(void* const* d_in, const int* in_sizes, int n_in,
                              void* d_out, int out_size)
{
    const float* x     = (const float*)d_in[0];
    const float* w_qkv = (const float*)d_in[1];
    const float* w_out = (const float*)d_in[2];
    const float* b_out = (const float*)d_in[3];
    float* out = (float*)d_out;

    cudaFuncSetAttribute(mma_kernel, cudaFuncAttributeMaxDynamicSharedMemorySize, SMEMB);

    transform_x<<<dim3(128, 8, 16), dim3(32, 8)>>>(x);
    wsplit<<<1536, 256>>>(w_qkv, w_out);
    mma_kernel<<<3 * KS * 16, 512, SMEMB>>>(MODE_SYRK, b_out, out);
    reduce_g<<<4096, 256>>>();
    mma_kernel<<<128,  512, SMEMB>>>(MODE_S1,    b_out, out);
    mma_kernel<<<128,  512, SMEMB>>>(MODE_S2,    b_out, out);
    mma_kernel<<<256,  512, SMEMB>>>(MODE_S3,    b_out, out);
    mma_kernel<<<64,   512, SMEMB>>>(MODE_S4,    b_out, out);
    mma_kernel<<<1024, 512, SMEMB>>>(MODE_FINAL, b_out, out);
}

// round 7
// speedup vs baseline: 1.5260x; 1.0133x over previous
#include <cuda_runtime.h>
#include <cuda_bf16.h>
#include <cstdint>

typedef __nv_bfloat16 bf16;

#define DIMC 256
#define NPIX 4096
#define BATCH 16
#define HID 512
#define NH 8
#define DH 64
#define KS 8                  // SYRK split-K slices

#define BK 32
#define LROW 40               // 32 + 8 pad bf16 (80B row, 16B-aligned, conflict-free)
#define TILEB (128 * LROW * 2)
#define STAGEB (4 * TILEB)    // 40960 B
#define NSTG 4
#define SMEMB (NSTG * STAGEB) // 163840 B

// ---------------- scratch (device globals) ----------------
__device__ float g_Gp[KS * BATCH * DIMC * DIMC];
__device__ bf16 g_Xhi [BATCH * DIMC * NPIX];
__device__ bf16 g_Xlo [BATCH * DIMC * NPIX];
__device__ bf16 g_XThi[BATCH * NPIX * DIMC];
__device__ bf16 g_XTlo[BATCH * NPIX * DIMC];
__device__ bf16 g_Ghi [BATCH * DIMC * DIMC];
__device__ bf16 g_Glo [BATCH * DIMC * DIMC];
__device__ bf16 g_Phi [BATCH * HID * DIMC];
__device__ bf16 g_Plo [BATCH * HID * DIMC];
__device__ bf16 g_CThi[BATCH * NH * DH * DH];
__device__ bf16 g_CTlo[BATCH * NH * DH * DH];
__device__ bf16 g_MThi[BATCH * DIMC * HID];
__device__ bf16 g_MTlo[BATCH * DIMC * HID];
__device__ bf16 g_Ahi [BATCH * DIMC * DIMC];
__device__ bf16 g_Alo [BATCH * DIMC * DIMC];
__device__ bf16 g_Wh  [3 * HID * DIMC];
__device__ bf16 g_Wl  [3 * HID * DIMC];
__device__ bf16 g_WOh [DIMC * HID];
__device__ bf16 g_WOl [DIMC * HID];
__device__ bf16 g_WqTh[NH * DIMC * DH];
__device__ bf16 g_WqTl[NH * DIMC * DH];

// ---------------- helpers ----------------
__device__ __forceinline__ void split2(float v, bf16& h, bf16& l) {
    h = __float2bfloat16(v);
    l = __float2bfloat16(v - __bfloat162float(h));
}
__device__ __forceinline__ uint32_t smem_u32(const void* p) {
    uint32_t a;
    asm("{ .reg .u64 t; cvta.to.shared.u64 t, %1; cvt.u32.u64 %0, t; }" : "=r"(a) : "l"(p));
    return a;
}
__device__ __forceinline__ void cp16(uint32_t dst, const bf16* src) {
    asm volatile("cp.async.cg.shared.global [%0], [%1], 16;" :: "r"(dst), "l"(src));
}
#define CP_COMMIT() asm volatile("cp.async.commit_group;" ::: "memory")
#define CP_WAIT2()  asm volatile("cp.async.wait_group 2;" ::: "memory")

#define LDSM4(r0, r1, r2, r3, a) \
    asm volatile("ldmatrix.sync.aligned.m8n8.x4.shared.b16 {%0,%1,%2,%3}, [%4];" \
                 : "=r"(r0), "=r"(r1), "=r"(r2), "=r"(r3) : "r"(a))

__device__ __forceinline__ void mma16816(float c[4],
                                         uint32_t a0, uint32_t a1, uint32_t a2, uint32_t a3,
                                         uint32_t b0, uint32_t b1) {
    asm volatile(
        "mma.sync.aligned.m16n8k16.row.col.f32.bf16.bf16.f32 "
        "{%0,%1,%2,%3},{%4,%5,%6,%7},{%8,%9},{%0,%1,%2,%3};"
        : "+f"(c[0]), "+f"(c[1]), "+f"(c[2]), "+f"(c[3])
        : "r"(a0), "r"(a1), "r"(a2), "r"(a3), "r"(b0), "r"(b1));
}

// ---------------- transforms ----------------
__global__ void transform_x(const float* __restrict__ x) {
    __shared__ float tile[32][33];
    int b = blockIdx.z, c0 = blockIdx.y * 32, n0 = blockIdx.x * 32;
    int tx = threadIdx.x, ty = threadIdx.y;   // 32 x 8
    const float* xb = x + (size_t)b * DIMC * NPIX;
    #pragma unroll
    for (int i = 0; i < 4; ++i) {
        int c = c0 + ty + i * 8, n = n0 + tx;
        float v = xb[(size_t)c * NPIX + n];
        tile[ty + i * 8][tx] = v;
        size_t o = (size_t)b * DIMC * NPIX + (size_t)c * NPIX + n;
        split2(v, g_Xhi[o], g_Xlo[o]);
    }
    __syncthreads();
    #pragma unroll
    for (int i = 0; i < 4; ++i) {
        int n = n0 + ty + i * 8, c = c0 + tx;
        float v = tile[tx][ty + i * 8];
        size_t o = (size_t)b * NPIX * DIMC + (size_t)n * DIMC + c;
        split2(v, g_XThi[o], g_XTlo[o]);
    }
}

__global__ void wsplit(const float* __restrict__ w_qkv, const float* __restrict__ w_out) {
    int idx = blockIdx.x * 256 + threadIdx.x;
    if (idx < 3 * HID * DIMC) split2(w_qkv[idx], g_Wh[idx], g_Wl[idx]);
    if (idx < DIMC * HID)     split2(w_out[idx], g_WOh[idx], g_WOl[idx]);
    if (idx < NH * DIMC * DH) {
        int d = idx & 63, c = (idx >> 6) & 255, h = idx >> 14;
        float v = 0.125f * w_qkv[(size_t)(h * 64 + d) * DIMC + c];
        split2(v, g_WqTh[idx], g_WqTl[idx]);
    }
}

__global__ void reduce_g() {
    int idx = blockIdx.x * 256 + threadIdx.x;          // 262144 float4s
    const size_t S4 = (size_t)BATCH * DIMC * DIMC / 4;
    const float4* p = (const float4*)g_Gp;
    float4 v = p[idx];
    #pragma unroll
    for (int s = 1; s < KS; ++s) {
        float4 t = p[idx + s * S4];
        v.x += t.x; v.y += t.y; v.z += t.z; v.w += t.w;
    }
    bf16 h0, l0, h1, l1, h2, l2, h3, l3;
    split2(v.x, h0, l0); split2(v.y, h1, l1);
    split2(v.z, h2, l2); split2(v.w, h3, l3);
    __nv_bfloat162 ph0 = {h0, h1}, ph1 = {h2, h3};
    __nv_bfloat162 pl0 = {l0, l1}, pl1 = {l2, l3};
    uint2 uh, ul;
    uh.x = *(uint32_t*)&ph0; uh.y = *(uint32_t*)&ph1;
    ul.x = *(uint32_t*)&pl0; ul.y = *(uint32_t*)&pl1;
    *(uint2*)&g_Ghi[4 * (size_t)idx] = uh;
    *(uint2*)&g_Glo[4 * (size_t)idx] = ul;
}

// ---------------- modes ----------------
#define MODE_SYRK  0
#define MODE_S1    1
#define MODE_S2    2
#define MODE_S3    3
#define MODE_S4    4
#define MODE_FINAL 5

#define EP_F32    0
#define EP_BIAS   1
#define EP_HILO   2
#define EP_HILO_T 3

__global__ void __launch_bounds__(512)
mma_kernel(int mode, const float* __restrict__ b_out, float* __restrict__ out)
{
    extern __shared__ char sm[];
    const int tid = threadIdx.x;
    const int lane = tid & 31, wid = tid >> 5;
    const int m0 = (wid >> 2) * 32, n0 = (wid & 3) * 32;   // 4x4 warps, 32x32 tiles
    const int bx = blockIdx.x;

    // ---- decode job ----
    const bf16 *Ahp, *Alp, *Bhp, *Blp;
    int lda, ldb, K, Ar, Br;
    int ep, orows = 128, ocols = 128, ldo;
    const float* bias = nullptr;
    float* eo32 = nullptr;
    float* em = nullptr;
    bf16 *eoh = nullptr, *eol = nullptr;

    if (mode == MODE_SYRK) {
        int p = bx % 3, ks = (bx / 3) & (KS - 1), b = bx / (3 * KS);
        int ti = (p == 2) ? 1 : 0;
        int tj = (p == 0) ? 0 : 1;
        size_t ao = ((size_t)b * DIMC + ti * 128) * NPIX + (size_t)ks * (NPIX / KS);
        size_t bo = ((size_t)b * DIMC + tj * 128) * NPIX + (size_t)ks * (NPIX / KS);
        Ahp = g_Xhi + ao; Alp = g_Xlo + ao; Bhp = g_Xhi + bo; Blp = g_Xlo + bo;
        lda = NPIX; ldb = NPIX; K = NPIX / KS; Ar = 128; Br = 128;
        ep = EP_F32; ldo = DIMC;
        float* Gp = g_Gp + ((size_t)ks * BATCH + b) * DIMC * DIMC;
        eo32 = Gp + (size_t)ti * 128 * DIMC + tj * 128;
        if (ti != tj) em = Gp + (size_t)tj * 128 * DIMC + ti * 128;
    } else if (mode == MODE_S1) {
        int nt = bx & 1, mt = (bx >> 1) & 3, b = bx >> 3;
        size_t ao = (size_t)(HID + mt * 128) * DIMC;
        size_t bo = (size_t)b * DIMC * DIMC + (size_t)nt * 128 * DIMC;   // G symmetric
        Ahp = g_Wh + ao; Alp = g_Wl + ao; Bhp = g_Ghi + bo; Blp = g_Glo + bo;
        lda = DIMC; ldb = DIMC; K = DIMC; Ar = 128; Br = 128;
        ep = EP_HILO; ldo = DIMC;
        size_t oo = (size_t)b * HID * DIMC + (size_t)mt * 128 * DIMC + nt * 128;
        eoh = g_Phi + oo; eol = g_Plo + oo;
    } else if (mode == MODE_S2) {
        int h = bx & 7, b = bx >> 3;
        size_t ao = (size_t)b * HID * DIMC + (size_t)h * 64 * DIMC;
        size_t bo = (size_t)(2 * HID + h * 64) * DIMC;
        Ahp = g_Phi + ao; Alp = g_Plo + ao; Bhp = g_Wh + bo; Blp = g_Wl + bo;
        lda = DIMC; ldb = DIMC; K = DIMC; Ar = 64; Br = 64;
        ep = EP_HILO_T; orows = 64; ocols = 64; ldo = 64;
        size_t oo = (size_t)bx * DH * DH;
        eoh = g_CThi + oo; eol = g_CTlo + oo;
    } else if (mode == MODE_S3) {
        int nt = bx & 1, bh = bx >> 1, h = bh & 7, b = bh >> 3;
        size_t ao = (size_t)bh * DH * DH;
        size_t bo = (size_t)h * DIMC * DH + (size_t)nt * 128 * DH;
        Ahp = g_CThi + ao; Alp = g_CTlo + ao; Bhp = g_WqTh + bo; Blp = g_WqTl + bo;
        lda = DH; ldb = DH; K = DH; Ar = 64; Br = 128;
        ep = EP_HILO_T; orows = 64; ocols = 128; ldo = HID;
        size_t oo = (size_t)b * DIMC * HID + (size_t)nt * 128 * HID + h * 64;
        eoh = g_MThi + oo; eol = g_MTlo + oo;
    } else if (mode == MODE_S4) {
        int nt = bx & 1, mt = (bx >> 1) & 1, b = bx >> 2;
        size_t ao = (size_t)mt * 128 * HID;
        size_t bo = (size_t)b * DIMC * HID + (size_t)nt * 128 * HID;
        Ahp = g_WOh + ao; Alp = g_WOl + ao; Bhp = g_MThi + bo; Blp = g_MTlo + bo;
        lda = HID; ldb = HID; K = HID; Ar = 128; Br = 128;
        ep = EP_HILO; ldo = DIMC;
        size_t oo = (size_t)b * DIMC * DIMC + (size_t)mt * 128 * DIMC + nt * 128;
        eoh = g_Ahi + oo; eol = g_Alo + oo;
    } else {  // MODE_FINAL
        int nt = bx & 31, mt = (bx >> 5) & 1, b = bx >> 6;
        size_t ao = (size_t)b * DIMC * DIMC + (size_t)mt * 128 * DIMC;
        size_t bo = (size_t)b * NPIX * DIMC + (size_t)nt * 128 * DIMC;
        Ahp = g_Ahi + ao; Alp = g_Alo + ao; Bhp = g_XThi + bo; Blp = g_XTlo + bo;
        lda = DIMC; ldb = DIMC; K = DIMC; Ar = 128; Br = 128;
        ep = EP_BIAS; ldo = NPIX;
        bias = b_out + mt * 128;
        eo32 = out + (size_t)b * DIMC * NPIX + (size_t)mt * 128 * NPIX + nt * 128;
    }

    // ---- cp.async loader setup ----
    const int lrow = tid >> 2, lq = tid & 3;            // 128 rows x 4 chunks of 8 bf16
    const int ra = lrow < Ar ? lrow : 0;
    const int rb = lrow < Br ? lrow : 0;
    const uint32_t sbase = smem_u32(sm);
    const uint32_t doff = (uint32_t)(lrow * LROW + lq * 8) * 2;

    const int nch = K >> 5;                   // >= 2 for all modes

    auto issue = [&](int c) {
        if (c < nch) {
            uint32_t stg = sbase + (uint32_t)(c & (NSTG - 1)) * STAGEB + doff;
            int k0 = c * BK + lq * 8;
            cp16(stg,             Ahp + (size_t)ra * lda + k0);
            cp16(stg + TILEB,     Alp + (size_t)ra * lda + k0);
            cp16(stg + 2 * TILEB, Bhp + (size_t)rb * ldb + k0);
            cp16(stg + 3 * TILEB, Blp + (size_t)rb * ldb + k0);
        }
        CP_COMMIT();
    };

    float acc[2][4][4];
    #pragma unroll
    for (int a = 0; a < 2; ++a)
        #pragma unroll
        for (int b2 = 0; b2 < 4; ++b2)
            #pragma unroll
            for (int c = 0; c < 4; ++c) acc[a][b2][c] = 0.0f;

    // ldmatrix per-lane byte offsets (within a tile)
    const uint32_t frow = (uint32_t)(lane & 15);
    const uint32_t fcol = (uint32_t)((lane >> 4) * 8);
    // A: rows m0+mi*16+frow ; B: rows n0+np*16+frow ; col s*16+fcol
    uint32_t aoff[2][2], boff[2][2];
    #pragma unroll
    for (int mi = 0; mi < 2; ++mi)
        #pragma unroll
        for (int s = 0; s < 2; ++s)
            aoff[mi][s] = (uint32_t)(((m0 + mi * 16 + frow) * LROW) + s * 16 + fcol) * 2;
    #pragma unroll
    for (int np = 0; np < 2; ++np)
        #pragma unroll
        for (int s = 0; s < 2; ++s)
            boff[np][s] = (uint32_t)(((n0 + np * 16 + frow) * LROW) + s * 16 + fcol) * 2;

    // prologue: fill 3 stages
    issue(0); issue(1); issue(2);

    for (int c = 0; c < nch; ++c) {
        CP_WAIT2();                            // stage c resident
        __syncthreads();                       // all warps: stage c visible, stage c-1 fully consumed
        issue(c + NSTG - 1);                   // refills slot (c-1)%NSTG

        const uint32_t stg = sbase + (uint32_t)(c & (NSTG - 1)) * STAGEB;
        #pragma unroll
        for (int s = 0; s < 2; ++s) {
            uint32_t ah[2][4], al[2][4];
            #pragma unroll
            for (int mi = 0; mi < 2; ++mi) {
                LDSM4(ah[mi][0], ah[mi][1], ah[mi][2], ah[mi][3], stg + aoff[mi][s]);
                LDSM4(al[mi][0], al[mi][1], al[mi][2], al[mi][3], stg + TILEB + aoff[mi][s]);
            }
            #pragma unroll
            for (int np = 0; np < 2; ++np) {
                uint32_t bh0e, bh0o, bh1e, bh1o, bl0e, bl0o, bl1e, bl1o;
                LDSM4(bh0e, bh0o, bh1e, bh1o, stg + 2 * TILEB + boff[np][s]);
                LDSM4(bl0e, bl0o, bl1e, bl1o, stg + 3 * TILEB + boff[np][s]);
                #pragma unroll
                for (int mi = 0; mi < 2; ++mi) {
                    mma16816(acc[mi][2*np],   ah[mi][0], ah[mi][1], ah[mi][2], ah[mi][3], bh0e, bh1e);
                    mma16816(acc[mi][2*np],   ah[mi][0], ah[mi][1], ah[mi][2], ah[mi][3], bl0e, bl1e);
                    mma16816(acc[mi][2*np],   al[mi][0], al[mi][1], al[mi][2], al[mi][3], bh0e, bh1e);
                    mma16816(acc[mi][2*np+1], ah[mi][0], ah[mi][1], ah[mi][2], ah[mi][3], bh0o, bh1o);
                    mma16816(acc[mi][2*np+1], ah[mi][0], ah[mi][1], ah[mi][2], ah[mi][3], bl0o, bl1o);
                    mma16816(acc[mi][2*np+1], al[mi][0], al[mi][1], al[mi][2], al[mi][3], bh0o, bh1o);
                }
            }
        }
    }

    // ---- epilogue ----
    const int gr = lane >> 2, gc = (lane & 3) * 2;
    #pragma unroll
    for (int mi = 0; mi < 2; ++mi) {
        #pragma unroll
        for (int ni = 0; ni < 4; ++ni) {
            int r = m0 + mi * 16 + gr;
            int c = n0 + ni * 8 + gc;
            if (r >= orows || c >= ocols) continue;
            float v0 = acc[mi][ni][0], v1 = acc[mi][ni][1];
            float v2 = acc[mi][ni][2], v3 = acc[mi][ni][3];
            if (ep == EP_BIAS) {
                float bl = bias[r], bh2 = bias[r + 8];
                v0 += bl; v1 += bl; v2 += bh2; v3 += bh2;
            }
            if (ep == EP_F32 || ep == EP_BIAS) {
                float2 p0 = {v0, v1}, p1 = {v2, v3};
                *(float2*)&eo32[(size_t)r * ldo + c] = p0;
                *(float2*)&eo32[(size_t)(r + 8) * ldo + c] = p1;
                if (em) {
                    em[(size_t)c * ldo + r] = v0;
                    em[(size_t)(c + 1) * ldo + r] = v1;
                    em[(size_t)c * ldo + r + 8] = v2;
                    em[(size_t)(c + 1) * ldo + r + 8] = v3;
                }
            } else if (ep == EP_HILO) {
                bf16 h0, l0, h1, l1, h2, l2, h3, l3;
                split2(v0, h0, l0); split2(v1, h1, l1);
                split2(v2, h2, l2); split2(v3, h3, l3);
                __nv_bfloat162 ph0 = {h0, h1}, pl0 = {l0, l1};
                __nv_bfloat162 ph1 = {h2, h3}, pl1 = {l2, l3};
                *(__nv_bfloat162*)&eoh[(size_t)r * ldo + c] = ph0;
                *(__nv_bfloat162*)&eol[(size_t)r * ldo + c] = pl0;
                *(__nv_bfloat162*)&eoh[(size_t)(r + 8) * ldo + c] = ph1;
                *(__nv_bfloat162*)&eol[(size_t)(r + 8) * ldo + c] = pl1;
            } else {   // EP_HILO_T : store transposed [col][row]
                bf16 h, l;
                split2(v0, h, l); eoh[(size_t)c * ldo + r] = h;       eol[(size_t)c * ldo + r] = l;
                split2(v1, h, l); eoh[(size_t)(c + 1) * ldo + r] = h; eol[(size_t)(c + 1) * ldo + r] = l;
                split2(v2, h, l); eoh[(size_t)c * ldo + r + 8] = h;   eol[(size_t)c * ldo + r + 8] = l;
                split2(v3, h, l); eoh[(size_t)(c + 1) * ldo + r + 8] = h; eol[(size_t)(c + 1) * ldo + r + 8] = l;
            }
        }
    }
}

// ---------------- launch ----------------
extern "C" void kernel_launch(void* const* d_in, const int* in_sizes, int n_in,
                              void* d_out, int out_size)
{
    const float* x     = (const float*)d_in[0];
    const float* w_qkv = (const float*)d_in[1];
    const float* w_out = (const float*)d_in[2];
    const float* b_out = (const float*)d_in[3];
    float* out = (float*)d_out;

    cudaFuncSetAttribute(mma_kernel, cudaFuncAttributeMaxDynamicSharedMemorySize, SMEMB);

    transform_x<<<dim3(128, 8, 16), dim3(32, 8)>>>(x);
    wsplit<<<1536, 256>>>(w_qkv, w_out);
    mma_kernel<<<3 * KS * 16, 512, SMEMB>>>(MODE_SYRK, b_out, out);
    reduce_g<<<1024, 256>>>();
    mma_kernel<<<128,  512, SMEMB>>>(MODE_S1,    b_out, out);
    mma_kernel<<<128,  512, SMEMB>>>(MODE_S2,    b_out, out);
    mma_kernel<<<256,  512, SMEMB>>>(MODE_S3,    b_out, out);
    mma_kernel<<<64,   512, SMEMB>>>(MODE_S4,    b_out, out);
    mma_kernel<<<1024, 512, SMEMB>>>(MODE_FINAL, b_out, out);
}

// round 9
// speedup vs baseline: 1.6211x; 1.0624x over previous
#include <cuda_runtime.h>
#include <cuda_bf16.h>
#include <cstdint>

typedef __nv_bfloat16 bf16;

#define DIMC 256
#define NPIX 4096
#define BATCH 16
#define HID 512
#define NH 8
#define DH 64
#define KS 8                  // SYRK split-K slices

#define BK 32
#define LROW 40               // 32 + 8 pad bf16 (80B row) for K-contig tiles
#define LROWT 136             // 128 + 8 pad bf16 (272B row) for trans-B tiles
#define TILEB (128 * LROW * 2)   // 10240 B  (also fits 32*136*2 = 8704 B trans tile)
#define STAGEB (4 * TILEB)    // 40960 B
#define NSTG 4
#define SMEMB (NSTG * STAGEB) // 163840 B

// ---------------- scratch (device globals) ----------------
__device__ float g_Gp[KS * BATCH * DIMC * DIMC];
__device__ bf16 g_Xhi [BATCH * DIMC * NPIX];
__device__ bf16 g_Xlo [BATCH * DIMC * NPIX];
__device__ bf16 g_Ghi [BATCH * DIMC * DIMC];
__device__ bf16 g_Glo [BATCH * DIMC * DIMC];
__device__ bf16 g_Phi [BATCH * HID * DIMC];
__device__ bf16 g_Plo [BATCH * HID * DIMC];
__device__ bf16 g_CThi[BATCH * NH * DH * DH];
__device__ bf16 g_CTlo[BATCH * NH * DH * DH];
__device__ bf16 g_MThi[BATCH * DIMC * HID];
__device__ bf16 g_MTlo[BATCH * DIMC * HID];
__device__ bf16 g_Ahi [BATCH * DIMC * DIMC];
__device__ bf16 g_Alo [BATCH * DIMC * DIMC];
__device__ bf16 g_Wh  [3 * HID * DIMC];
__device__ bf16 g_Wl  [3 * HID * DIMC];
__device__ bf16 g_WOh [DIMC * HID];
__device__ bf16 g_WOl [DIMC * HID];
__device__ bf16 g_WqTh[NH * DIMC * DH];
__device__ bf16 g_WqTl[NH * DIMC * DH];

// ---------------- helpers ----------------
__device__ __forceinline__ void split2(float v, bf16& h, bf16& l) {
    h = __float2bfloat16(v);
    l = __float2bfloat16(v - __bfloat162float(h));
}
__device__ __forceinline__ uint32_t smem_u32(const void* p) {
    uint32_t a;
    asm("{ .reg .u64 t; cvta.to.shared.u64 t, %1; cvt.u32.u64 %0, t; }" : "=r"(a) : "l"(p));
    return a;
}
__device__ __forceinline__ void cp16(uint32_t dst, const bf16* src) {
    asm volatile("cp.async.cg.shared.global [%0], [%1], 16;" :: "r"(dst), "l"(src));
}
#define CP_COMMIT() asm volatile("cp.async.commit_group;" ::: "memory")
#define CP_WAIT2()  asm volatile("cp.async.wait_group 2;" ::: "memory")

#define LDSM4(r0, r1, r2, r3, a) \
    asm volatile("ldmatrix.sync.aligned.m8n8.x4.shared.b16 {%0,%1,%2,%3}, [%4];" \
                 : "=r"(r0), "=r"(r1), "=r"(r2), "=r"(r3) : "r"(a))
#define LDSM4T(r0, r1, r2, r3, a) \
    asm volatile("ldmatrix.sync.aligned.m8n8.x4.trans.shared.b16 {%0,%1,%2,%3}, [%4];" \
                 : "=r"(r0), "=r"(r1), "=r"(r2), "=r"(r3) : "r"(a))

__device__ __forceinline__ void mma16816(float c[4],
                                         uint32_t a0, uint32_t a1, uint32_t a2, uint32_t a3,
                                         uint32_t b0, uint32_t b1) {
    asm volatile(
        "mma.sync.aligned.m16n8k16.row.col.f32.bf16.bf16.f32 "
        "{%0,%1,%2,%3},{%4,%5,%6,%7},{%8,%9},{%0,%1,%2,%3};"
        : "+f"(c[0]), "+f"(c[1]), "+f"(c[2]), "+f"(c[3])
        : "r"(a0), "r"(a1), "r"(a2), "r"(a3), "r"(b0), "r"(b1));
}

// ---------------- transforms ----------------
// pure streaming: x fp32 -> X hi/lo bf16, fully coalesced, no smem
__global__ void transform_x(const float* __restrict__ x) {
    size_t idx = ((size_t)blockIdx.x * 256 + threadIdx.x) * 4;   // float index
    const size_t total = (size_t)BATCH * DIMC * NPIX;
    #pragma unroll
    for (int r = 0; r < 4; ++r, idx += (size_t)gridDim.x * 1024) {
        if (idx >= total) break;
        float4 v = *(const float4*)(x + idx);
        bf16 h0, l0, h1, l1, h2, l2, h3, l3;
        split2(v.x, h0, l0); split2(v.y, h1, l1);
        split2(v.z, h2, l2); split2(v.w, h3, l3);
        __nv_bfloat162 ph0 = {h0, h1}, ph1 = {h2, h3};
        __nv_bfloat162 pl0 = {l0, l1}, pl1 = {l2, l3};
        uint2 uh, ul;
        uh.x = *(uint32_t*)&ph0; uh.y = *(uint32_t*)&ph1;
        ul.x = *(uint32_t*)&pl0; ul.y = *(uint32_t*)&pl1;
        *(uint2*)&g_Xhi[idx] = uh;
        *(uint2*)&g_Xlo[idx] = ul;
    }
}

__global__ void wsplit(const float* __restrict__ w_qkv, const float* __restrict__ w_out) {
    int idx = blockIdx.x * 256 + threadIdx.x;
    if (idx < 3 * HID * DIMC) split2(w_qkv[idx], g_Wh[idx], g_Wl[idx]);
    if (idx < DIMC * HID)     split2(w_out[idx], g_WOh[idx], g_WOl[idx]);
    if (idx < NH * DIMC * DH) {
        int d = idx & 63, c = (idx >> 6) & 255, h = idx >> 14;
        float v = 0.125f * w_qkv[(size_t)(h * 64 + d) * DIMC + c];
        split2(v, g_WqTh[idx], g_WqTl[idx]);
    }
}

__global__ void reduce_g() {
    int idx = blockIdx.x * 256 + threadIdx.x;          // 262144 float4s
    const size_t S4 = (size_t)BATCH * DIMC * DIMC / 4;
    const float4* p = (const float4*)g_Gp;
    float4 v = p[idx];
    #pragma unroll
    for (int s = 1; s < KS; ++s) {
        float4 t = p[idx + s * S4];
        v.x += t.x; v.y += t.y; v.z += t.z; v.w += t.w;
    }
    bf16 h0, l0, h1, l1, h2, l2, h3, l3;
    split2(v.x, h0, l0); split2(v.y, h1, l1);
    split2(v.z, h2, l2); split2(v.w, h3, l3);
    __nv_bfloat162 ph0 = {h0, h1}, ph1 = {h2, h3};
    __nv_bfloat162 pl0 = {l0, l1}, pl1 = {l2, l3};
    uint2 uh, ul;
    uh.x = *(uint32_t*)&ph0; uh.y = *(uint32_t*)&ph1;
    ul.x = *(uint32_t*)&pl0; ul.y = *(uint32_t*)&pl1;
    *(uint2*)&g_Ghi[4 * (size_t)idx] = uh;
    *(uint2*)&g_Glo[4 * (size_t)idx] = ul;
}

// ---------------- modes ----------------
#define MODE_SYRK  0
#define MODE_S1    1
#define MODE_S2    2
#define MODE_S3    3
#define MODE_S4    4
#define MODE_FINAL 5

#define EP_F32    0
#define EP_BIAS   1
#define EP_HILO   2
#define EP_HILO_T 3

__global__ void __launch_bounds__(512)
mma_kernel(int mode, const float* __restrict__ b_out, float* __restrict__ out)
{
    extern __shared__ char sm[];
    const int tid = threadIdx.x;
    const int lane = tid & 31, wid = tid >> 5;
    const int m0 = (wid >> 2) * 32, n0 = (wid & 3) * 32;   // 4x4 warps, 32x32 tiles
    const int bx = blockIdx.x;

    // ---- decode job ----
    const bf16 *Ahp, *Alp, *Bhp, *Blp;
    int lda, ldb, K, Ar, Br;
    int ep, orows = 128, ocols = 128, ldo;
    bool btr = false;                       // B tile is [K][N] (trans-ldmatrix)
    const float* bias = nullptr;
    float* eo32 = nullptr;
    float* em = nullptr;
    bf16 *eoh = nullptr, *eol = nullptr;

    if (mode == MODE_SYRK) {
        int p = bx % 3, ks = (bx / 3) & (KS - 1), b = bx / (3 * KS);
        int ti = (p == 2) ? 1 : 0;
        int tj = (p == 0) ? 0 : 1;
        size_t ao = ((size_t)b * DIMC + ti * 128) * NPIX + (size_t)ks * (NPIX / KS);
        size_t bo = ((size_t)b * DIMC + tj * 128) * NPIX + (size_t)ks * (NPIX / KS);
        Ahp = g_Xhi + ao; Alp = g_Xlo + ao; Bhp = g_Xhi + bo; Blp = g_Xlo + bo;
        lda = NPIX; ldb = NPIX; K = NPIX / KS; Ar = 128; Br = 128;
        ep = EP_F32; ldo = DIMC;
        float* Gp = g_Gp + ((size_t)ks * BATCH + b) * DIMC * DIMC;
        eo32 = Gp + (size_t)ti * 128 * DIMC + tj * 128;
        if (ti != tj) em = Gp + (size_t)tj * 128 * DIMC + ti * 128;
    } else if (mode == MODE_S1) {
        int mt = bx & 3, nt = (bx >> 2) & 1, b = bx >> 3;    // mt fastest: share G tile
        size_t ao = (size_t)(HID + mt * 128) * DIMC;
        size_t bo = (size_t)b * DIMC * DIMC + (size_t)nt * 128 * DIMC;   // G symmetric
        Ahp = g_Wh + ao; Alp = g_Wl + ao; Bhp = g_Ghi + bo; Blp = g_Glo + bo;
        lda = DIMC; ldb = DIMC; K = DIMC; Ar = 128; Br = 128;
        ep = EP_HILO; ldo = DIMC;
        size_t oo = (size_t)b * HID * DIMC + (size_t)mt * 128 * DIMC + nt * 128;
        eoh = g_Phi + oo; eol = g_Plo + oo;
    } else if (mode == MODE_S2) {
        int h = bx & 7, b = bx >> 3;
        size_t ao = (size_t)b * HID * DIMC + (size_t)h * 64 * DIMC;
        size_t bo = (size_t)(2 * HID + h * 64) * DIMC;
        Ahp = g_Phi + ao; Alp = g_Plo + ao; Bhp = g_Wh + bo; Blp = g_Wl + bo;
        lda = DIMC; ldb = DIMC; K = DIMC; Ar = 64; Br = 64;
        ep = EP_HILO_T; orows = 64; ocols = 64; ldo = 64;
        size_t oo = (size_t)bx * DH * DH;
        eoh = g_CThi + oo; eol = g_CTlo + oo;
    } else if (mode == MODE_S3) {
        int nt = bx & 1, bh = bx >> 1, h = bh & 7, b = bh >> 3;
        size_t ao = (size_t)bh * DH * DH;
        size_t bo = (size_t)h * DIMC * DH + (size_t)nt * 128 * DH;
        Ahp = g_CThi + ao; Alp = g_CTlo + ao; Bhp = g_WqTh + bo; Blp = g_WqTl + bo;
        lda = DH; ldb = DH; K = DH; Ar = 64; Br = 128;
        ep = EP_HILO_T; orows = 64; ocols = 128; ldo = HID;
        size_t oo = (size_t)b * DIMC * HID + (size_t)nt * 128 * HID + h * 64;
        eoh = g_MThi + oo; eol = g_MTlo + oo;
    } else if (mode == MODE_S4) {
        int nt = bx & 1, mt = (bx >> 1) & 1, b = bx >> 2;
        size_t ao = (size_t)mt * 128 * HID;
        size_t bo = (size_t)b * DIMC * HID + (size_t)nt * 128 * HID;
        Ahp = g_WOh + ao; Alp = g_WOl + ao; Bhp = g_MThi + bo; Blp = g_MTlo + bo;
        lda = HID; ldb = HID; K = HID; Ar = 128; Br = 128;
        ep = EP_HILO; ldo = DIMC;
        size_t oo = (size_t)b * DIMC * DIMC + (size_t)mt * 128 * DIMC + nt * 128;
        eoh = g_Ahi + oo; eol = g_Alo + oo;
    } else {  // MODE_FINAL: B = X[c][pix] via trans-ldmatrix; mt fastest for L2 share
        int mt = bx & 1, nt = (bx >> 1) & 31, b = bx >> 6;
        size_t ao = (size_t)b * DIMC * DIMC + (size_t)mt * 128 * DIMC;
        size_t bo = (size_t)b * DIMC * NPIX + (size_t)nt * 128;   // rows=c (K), cols=pix
        Ahp = g_Ahi + ao; Alp = g_Alo + ao; Bhp = g_Xhi + bo; Blp = g_Xlo + bo;
        lda = DIMC; ldb = NPIX; K = DIMC; Ar = 128; Br = 128;
        btr = true;
        ep = EP_BIAS; ldo = NPIX;
        bias = b_out + mt * 128;
        eo32 = out + (size_t)b * DIMC * NPIX + (size_t)mt * 128 * NPIX + nt * 128;
    }

    // ---- cp.async loader setup ----
    const int lrow = tid >> 2, lq = tid & 3;            // KC tiles: 128 rows x 4 chunks
    const int ra = lrow < Ar ? lrow : 0;
    const int rb = lrow < Br ? lrow : 0;
    const uint32_t sbase = smem_u32(sm);
    const uint32_t doff  = (uint32_t)(lrow * LROW + lq * 8) * 2;
    // trans tiles: 32 k-rows x 16 chunks of 8 bf16
    const int trow = tid >> 4, tq = tid & 15;
    const uint32_t dofft = (uint32_t)(trow * LROWT + tq * 8) * 2;

    const int nch = K >> 5;

    auto issue = [&](int c) {
        if (c < nch) {
            uint32_t stg = sbase + (uint32_t)(c & (NSTG - 1)) * STAGEB;
            int k0 = c * BK;
            cp16(stg + doff,         Ahp + (size_t)ra * lda + k0 + lq * 8);
            cp16(stg + TILEB + doff, Alp + (size_t)ra * lda + k0 + lq * 8);
            if (btr) {
                const bf16* bsrc = Bhp + (size_t)(k0 + trow) * ldb + tq * 8;
                const bf16* lsrc = Blp + (size_t)(k0 + trow) * ldb + tq * 8;
                cp16(stg + 2 * TILEB + dofft, bsrc);
                cp16(stg + 3 * TILEB + dofft, lsrc);
            } else {
                cp16(stg + 2 * TILEB + doff, Bhp + (size_t)rb * ldb + k0 + lq * 8);
                cp16(stg + 3 * TILEB + doff, Blp + (size_t)rb * ldb + k0 + lq * 8);
            }
        }
        CP_COMMIT();
    };

    float acc[2][4][4];
    #pragma unroll
    for (int a = 0; a < 2; ++a)
        #pragma unroll
        for (int b2 = 0; b2 < 4; ++b2)
            #pragma unroll
            for (int c = 0; c < 4; ++c) acc[a][b2][c] = 0.0f;

    // ldmatrix per-lane byte offsets (within a tile)
    const uint32_t frow = (uint32_t)(lane & 15);
    const uint32_t fcol = (uint32_t)((lane >> 4) * 8);
    uint32_t aoff[2][2], boff[2][2];
    #pragma unroll
    for (int mi = 0; mi < 2; ++mi)
        #pragma unroll
        for (int s = 0; s < 2; ++s)
            aoff[mi][s] = (uint32_t)(((m0 + mi * 16 + frow) * LROW) + s * 16 + fcol) * 2;
    if (btr) {
        #pragma unroll
        for (int np = 0; np < 2; ++np)
            #pragma unroll
            for (int s = 0; s < 2; ++s)
                boff[np][s] = (uint32_t)((s * 16 + frow) * LROWT + n0 + np * 16 + fcol) * 2;
    } else {
        #pragma unroll
        for (int np = 0; np < 2; ++np)
            #pragma unroll
            for (int s = 0; s < 2; ++s)
                boff[np][s] = (uint32_t)(((n0 + np * 16 + frow) * LROW) + s * 16 + fcol) * 2;
    }

    issue(0); issue(1); issue(2);

    for (int c = 0; c < nch; ++c) {
        CP_WAIT2();
        __syncthreads();
        issue(c + NSTG - 1);

        const uint32_t stg = sbase + (uint32_t)(c & (NSTG - 1)) * STAGEB;
        #pragma unroll
        for (int s = 0; s < 2; ++s) {
            uint32_t ah[2][4], al[2][4];
            #pragma unroll
            for (int mi = 0; mi < 2; ++mi) {
                LDSM4(ah[mi][0], ah[mi][1], ah[mi][2], ah[mi][3], stg + aoff[mi][s]);
                LDSM4(al[mi][0], al[mi][1], al[mi][2], al[mi][3], stg + TILEB + aoff[mi][s]);
            }
            #pragma unroll
            for (int np = 0; np < 2; ++np) {
                uint32_t bh0e, bh0o, bh1e, bh1o, bl0e, bl0o, bl1e, bl1o;
                if (btr) {
                    LDSM4T(bh0e, bh1e, bh0o, bh1o, stg + 2 * TILEB + boff[np][s]);
                    LDSM4T(bl0e, bl1e, bl0o, bl1o, stg + 3 * TILEB + boff[np][s]);
                } else {
                    LDSM4(bh0e, bh0o, bh1e, bh1o, stg + 2 * TILEB + boff[np][s]);
                    LDSM4(bl0e, bl0o, bl1e, bl1o, stg + 3 * TILEB + boff[np][s]);
                }
                #pragma unroll
                for (int mi = 0; mi < 2; ++mi) {
                    mma16816(acc[mi][2*np],   ah[mi][0], ah[mi][1], ah[mi][2], ah[mi][3], bh0e, bh1e);
                    mma16816(acc[mi][2*np],   ah[mi][0], ah[mi][1], ah[mi][2], ah[mi][3], bl0e, bl1e);
                    mma16816(acc[mi][2*np],   al[mi][0], al[mi][1], al[mi][2], al[mi][3], bh0e, bh1e);
                    mma16816(acc[mi][2*np+1], ah[mi][0], ah[mi][1], ah[mi][2], ah[mi][3], bh0o, bh1o);
                    mma16816(acc[mi][2*np+1], ah[mi][0], ah[mi][1], ah[mi][2], ah[mi][3], bl0o, bl1o);
                    mma16816(acc[mi][2*np+1], al[mi][0], al[mi][1], al[mi][2], al[mi][3], bh0o, bh1o);
                }
            }
        }
    }

    // ---- epilogue ----
    const int gr = lane >> 2, gc = (lane & 3) * 2;
    #pragma unroll
    for (int mi = 0; mi < 2; ++mi) {
        #pragma unroll
        for (int ni = 0; ni < 4; ++ni) {
            int r = m0 + mi * 16 + gr;
            int c = n0 + ni * 8 + gc;
            if (r >= orows || c >= ocols) continue;
            float v0 = acc[mi][ni][0], v1 = acc[mi][ni][1];
            float v2 = acc[mi][ni][2], v3 = acc[mi][ni][3];
            if (ep == EP_BIAS) {
                float bl = bias[r], bh2 = bias[r + 8];
                v0 += bl; v1 += bl; v2 += bh2; v3 += bh2;
            }
            if (ep == EP_F32 || ep == EP_BIAS) {
                float2 p0 = {v0, v1}, p1 = {v2, v3};
                *(float2*)&eo32[(size_t)r * ldo + c] = p0;
                *(float2*)&eo32[(size_t)(r + 8) * ldo + c] = p1;
                if (em) {
                    em[(size_t)c * ldo + r] = v0;
                    em[(size_t)(c + 1) * ldo + r] = v1;
                    em[(size_t)c * ldo + r + 8] = v2;
                    em[(size_t)(c + 1) * ldo + r + 8] = v3;
                }
            } else if (ep == EP_HILO) {
                bf16 h0, l0, h1, l1, h2, l2, h3, l3;
                split2(v0, h0, l0); split2(v1, h1, l1);
                split2(v2, h2, l2); split2(v3, h3, l3);
                __nv_bfloat162 ph0 = {h0, h1}, pl0 = {l0, l1};
                __nv_bfloat162 ph1 = {h2, h3}, pl1 = {l2, l3};
                *(__nv_bfloat162*)&eoh[(size_t)r * ldo + c] = ph0;
                *(__nv_bfloat162*)&eol[(size_t)r * ldo + c] = pl0;
                *(__nv_bfloat162*)&eoh[(size_t)(r + 8) * ldo + c] = ph1;
                *(__nv_bfloat162*)&eol[(size_t)(r + 8) * ldo + c] = pl1;
            } else {   // EP_HILO_T : store transposed [col][row]
                bf16 h, l;
                split2(v0, h, l); eoh[(size_t)c * ldo + r] = h;       eol[(size_t)c * ldo + r] = l;
                split2(v1, h, l); eoh[(size_t)(c + 1) * ldo + r] = h; eol[(size_t)(c + 1) * ldo + r] = l;
                split2(v2, h, l); eoh[(size_t)c * ldo + r + 8] = h;   eol[(size_t)c * ldo + r + 8] = l;
                split2(v3, h, l); eoh[(size_t)(c + 1) * ldo + r + 8] = h; eol[(size_t)(c + 1) * ldo + r + 8] = l;
            }
        }
    }
}

// ---------------- launch ----------------
extern "C" void kernel_launch(void* const* d_in, const int* in_sizes, int n_in,
                              void* d_out, int out_size)
{
    const float* x     = (const float*)d_in[0];
    const float* w_qkv = (const float*)d_in[1];
    const float* w_out = (const float*)d_in[2];
    const float* b_out = (const float*)d_in[3];
    float* out = (float*)d_out;

    cudaFuncSetAttribute(mma_kernel, cudaFuncAttributeMaxDynamicSharedMemorySize, SMEMB);

    transform_x<<<4096, 256>>>(x);     // 4096*256*16 = 16,777,216 floats = |x|
    wsplit<<<1536, 256>>>(w_qkv, w_out);
    mma_kernel<<<3 * KS * 16, 512, SMEMB>>>(MODE_SYRK, b_out, out);
    reduce_g<<<1024, 256>>>();
    mma_kernel<<<128,  512, SMEMB>>>(MODE_S1,    b_out, out);
    mma_kernel<<<128,  512, SMEMB>>>(MODE_S2,    b_out, out);
    mma_kernel<<<256,  512, SMEMB>>>(MODE_S3,    b_out, out);
    mma_kernel<<<64,   512, SMEMB>>>(MODE_S4,    b_out, out);
    mma_kernel<<<1024, 512, SMEMB>>>(MODE_FINAL, b_out, out);
}

// round 10
// speedup vs baseline: 1.8119x; 1.1177x over previous
#include <cuda_runtime.h>
#include <cuda_bf16.h>
#include <cstdint>

typedef __nv_bfloat16 bf16;

#define DIMC 256
#define NPIX 4096
#define BATCH 16
#define HID 512
#define NH 8
#define DH 64
#define KS 8                  // SYRK split-K slices

#define BK 32
#define LROW 40               // bf16 tiles: 32 + 8 pad (80B row)
#define LROW4 36              // tf32 tiles: 32 + 4 pad fp32 (144B row)
#define TILEB (128 * LROW * 2)      // 10240 B (bf16 tile)
#define TILE4B (128 * LROW4 * 4)    // 18432 B (tf32 tile)
#define STAGEB (4 * TILEB)    // 40960 B (covers 2*TILE4B=36864 too)
#define NSTG 4
#define SMEMB (NSTG * STAGEB) // 163840 B

// ---------------- scratch (device globals) ----------------
__device__ float g_Gp [KS * BATCH * DIMC * DIMC];
__device__ float g_Xr [BATCH * DIMC * NPIX];    // rna(x), [b][c][n]
__device__ float g_XTr[BATCH * NPIX * DIMC];    // rna(x) transposed, [b][n][c]
__device__ float g_A  [BATCH * DIMC * DIMC];    // A_b fp32 (rna-rounded)
__device__ bf16 g_Ghi [BATCH * DIMC * DIMC];
__device__ bf16 g_Glo [BATCH * DIMC * DIMC];
__device__ bf16 g_Phi [BATCH * HID * DIMC];
__device__ bf16 g_Plo [BATCH * HID * DIMC];
__device__ bf16 g_CThi[BATCH * NH * DH * DH];
__device__ bf16 g_CTlo[BATCH * NH * DH * DH];
__device__ bf16 g_MThi[BATCH * DIMC * HID];
__device__ bf16 g_MTlo[BATCH * DIMC * HID];
__device__ bf16 g_Wh  [3 * HID * DIMC];
__device__ bf16 g_Wl  [3 * HID * DIMC];
__device__ bf16 g_WOh [DIMC * HID];
__device__ bf16 g_WOl [DIMC * HID];
__device__ bf16 g_WqTh[NH * DIMC * DH];
__device__ bf16 g_WqTl[NH * DIMC * DH];

// ---------------- helpers ----------------
__device__ __forceinline__ void split2(float v, bf16& h, bf16& l) {
    h = __float2bfloat16(v);
    l = __float2bfloat16(v - __bfloat162float(h));
}
__device__ __forceinline__ float rna_tf32(float v) {
    uint32_t r;
    asm("cvt.rna.tf32.f32 %0, %1;" : "=r"(r) : "f"(v));
    return __uint_as_float(r);
}
__device__ __forceinline__ uint32_t smem_u32(const void* p) {
    uint32_t a;
    asm("{ .reg .u64 t; cvta.to.shared.u64 t, %1; cvt.u32.u64 %0, t; }" : "=r"(a) : "l"(p));
    return a;
}
__device__ __forceinline__ void cp16(uint32_t dst, const void* src) {
    asm volatile("cp.async.cg.shared.global [%0], [%1], 16;" :: "r"(dst), "l"(src));
}
#define CP_COMMIT() asm volatile("cp.async.commit_group;" ::: "memory")
#define CP_WAIT2()  asm volatile("cp.async.wait_group 2;" ::: "memory")

#define LDSM4(r0, r1, r2, r3, a) \
    asm volatile("ldmatrix.sync.aligned.m8n8.x4.shared.b16 {%0,%1,%2,%3}, [%4];" \
                 : "=r"(r0), "=r"(r1), "=r"(r2), "=r"(r3) : "r"(a))

__device__ __forceinline__ void mma16816(float c[4],
                                         uint32_t a0, uint32_t a1, uint32_t a2, uint32_t a3,
                                         uint32_t b0, uint32_t b1) {
    asm volatile(
        "mma.sync.aligned.m16n8k16.row.col.f32.bf16.bf16.f32 "
        "{%0,%1,%2,%3},{%4,%5,%6,%7},{%8,%9},{%0,%1,%2,%3};"
        : "+f"(c[0]), "+f"(c[1]), "+f"(c[2]), "+f"(c[3])
        : "r"(a0), "r"(a1), "r"(a2), "r"(a3), "r"(b0), "r"(b1));
}
__device__ __forceinline__ void mma1688t(float c[4],
                                         uint32_t a0, uint32_t a1, uint32_t a2, uint32_t a3,
                                         uint32_t b0, uint32_t b1) {
    asm volatile(
        "mma.sync.aligned.m16n8k8.row.col.f32.tf32.tf32.f32 "
        "{%0,%1,%2,%3},{%4,%5,%6,%7},{%8,%9},{%0,%1,%2,%3};"
        : "+f"(c[0]), "+f"(c[1]), "+f"(c[2]), "+f"(c[3])
        : "r"(a0), "r"(a1), "r"(a2), "r"(a3), "r"(b0), "r"(b1));
}

// ---------------- transforms ----------------
// x fp32 -> rna-rounded Xr (same layout) + XTr (transposed)
__global__ void transform_x(const float* __restrict__ x) {
    __shared__ float tile[32][33];
    int b = blockIdx.z, c0 = blockIdx.y * 32, n0 = blockIdx.x * 32;
    int tx = threadIdx.x, ty = threadIdx.y;   // 32 x 8
    const float* xb = x + (size_t)b * DIMC * NPIX;
    #pragma unroll
    for (int i = 0; i < 4; ++i) {
        int c = c0 + ty + i * 8, n = n0 + tx;
        float r = rna_tf32(xb[(size_t)c * NPIX + n]);
        tile[ty + i * 8][tx] = r;
        g_Xr[(size_t)b * DIMC * NPIX + (size_t)c * NPIX + n] = r;
    }
    __syncthreads();
    #pragma unroll
    for (int i = 0; i < 4; ++i) {
        int n = n0 + ty + i * 8, c = c0 + tx;
        g_XTr[(size_t)b * NPIX * DIMC + (size_t)n * DIMC + c] = tile[tx][ty + i * 8];
    }
}

__global__ void wsplit(const float* __restrict__ w_qkv, const float* __restrict__ w_out) {
    int idx = blockIdx.x * 256 + threadIdx.x;
    if (idx < 3 * HID * DIMC) split2(w_qkv[idx], g_Wh[idx], g_Wl[idx]);
    if (idx < DIMC * HID)     split2(w_out[idx], g_WOh[idx], g_WOl[idx]);
    if (idx < NH * DIMC * DH) {
        int d = idx & 63, c = (idx >> 6) & 255, h = idx >> 14;
        float v = 0.125f * w_qkv[(size_t)(h * 64 + d) * DIMC + c];
        split2(v, g_WqTh[idx], g_WqTl[idx]);
    }
}

__global__ void reduce_g() {
    int idx = blockIdx.x * 256 + threadIdx.x;          // 262144 float4s
    const size_t S4 = (size_t)BATCH * DIMC * DIMC / 4;
    const float4* p = (const float4*)g_Gp;
    float4 v = p[idx];
    #pragma unroll
    for (int s = 1; s < KS; ++s) {
        float4 t = p[idx + s * S4];
        v.x += t.x; v.y += t.y; v.z += t.z; v.w += t.w;
    }
    bf16 h0, l0, h1, l1, h2, l2, h3, l3;
    split2(v.x, h0, l0); split2(v.y, h1, l1);
    split2(v.z, h2, l2); split2(v.w, h3, l3);
    __nv_bfloat162 ph0 = {h0, h1}, ph1 = {h2, h3};
    __nv_bfloat162 pl0 = {l0, l1}, pl1 = {l2, l3};
    uint2 uh, ul;
    uh.x = *(uint32_t*)&ph0; uh.y = *(uint32_t*)&ph1;
    ul.x = *(uint32_t*)&pl0; ul.y = *(uint32_t*)&pl1;
    *(uint2*)&g_Ghi[4 * (size_t)idx] = uh;
    *(uint2*)&g_Glo[4 * (size_t)idx] = ul;
}

// ---------------- modes ----------------
#define MODE_SYRK  0
#define MODE_S1    1
#define MODE_S2    2
#define MODE_S3    3
#define MODE_S4    4
#define MODE_FINAL 5

#define EP_F32    0
#define EP_BIAS   1
#define EP_HILO   2
#define EP_HILO_T 3
#define EP_F32R   4

__global__ void __launch_bounds__(512)
mma_kernel(int mode, const float* __restrict__ b_out, float* __restrict__ out)
{
    extern __shared__ char sm[];
    const int tid = threadIdx.x;
    const int lane = tid & 31, wid = tid >> 5;
    const int m0 = (wid >> 2) * 32, n0 = (wid & 3) * 32;   // 4x4 warps, 32x32 tiles
    const int bx = blockIdx.x;

    // ---- decode job ----
    const bf16 *Ahp = nullptr, *Alp = nullptr, *Bhp = nullptr, *Blp = nullptr;
    const float *Af = nullptr, *Bf = nullptr;     // tf32 operands
    int lda, ldb, K, Ar = 128, Br = 128;
    int ep, orows = 128, ocols = 128, ldo;
    bool tf32m = false;
    const float* bias = nullptr;
    float* eo32 = nullptr;
    float* em = nullptr;
    bf16 *eoh = nullptr, *eol = nullptr;

    if (mode == MODE_SYRK) {
        int p = bx % 3, ks = (bx / 3) & (KS - 1), b = bx / (3 * KS);
        int ti = (p == 2) ? 1 : 0;
        int tj = (p == 0) ? 0 : 1;
        size_t ao = ((size_t)b * DIMC + ti * 128) * NPIX + (size_t)ks * (NPIX / KS);
        size_t bo = ((size_t)b * DIMC + tj * 128) * NPIX + (size_t)ks * (NPIX / KS);
        Af = g_Xr + ao; Bf = g_Xr + bo;
        tf32m = true;
        lda = NPIX; ldb = NPIX; K = NPIX / KS;
        ep = EP_F32; ldo = DIMC;
        float* Gp = g_Gp + ((size_t)ks * BATCH + b) * DIMC * DIMC;
        eo32 = Gp + (size_t)ti * 128 * DIMC + tj * 128;
        if (ti != tj) em = Gp + (size_t)tj * 128 * DIMC + ti * 128;
    } else if (mode == MODE_S1) {
        int mt = bx & 3, nt = (bx >> 2) & 1, b = bx >> 3;
        size_t ao = (size_t)(HID + mt * 128) * DIMC;
        size_t bo = (size_t)b * DIMC * DIMC + (size_t)nt * 128 * DIMC;   // G symmetric
        Ahp = g_Wh + ao; Alp = g_Wl + ao; Bhp = g_Ghi + bo; Blp = g_Glo + bo;
        lda = DIMC; ldb = DIMC; K = DIMC;
        ep = EP_HILO; ldo = DIMC;
        size_t oo = (size_t)b * HID * DIMC + (size_t)mt * 128 * DIMC + nt * 128;
        eoh = g_Phi + oo; eol = g_Plo + oo;
    } else if (mode == MODE_S2) {
        int h = bx & 7, b = bx >> 3;
        size_t ao = (size_t)b * HID * DIMC + (size_t)h * 64 * DIMC;
        size_t bo = (size_t)(2 * HID + h * 64) * DIMC;
        Ahp = g_Phi + ao; Alp = g_Plo + ao; Bhp = g_Wh + bo; Blp = g_Wl + bo;
        lda = DIMC; ldb = DIMC; K = DIMC; Ar = 64; Br = 64;
        ep = EP_HILO_T; orows = 64; ocols = 64; ldo = 64;
        size_t oo = (size_t)bx * DH * DH;
        eoh = g_CThi + oo; eol = g_CTlo + oo;
    } else if (mode == MODE_S3) {
        int nt = bx & 1, bh = bx >> 1, h = bh & 7, b = bh >> 3;
        size_t ao = (size_t)bh * DH * DH;
        size_t bo = (size_t)h * DIMC * DH + (size_t)nt * 128 * DH;
        Ahp = g_CThi + ao; Alp = g_CTlo + ao; Bhp = g_WqTh + bo; Blp = g_WqTl + bo;
        lda = DH; ldb = DH; K = DH; Ar = 64; Br = 128;
        ep = EP_HILO_T; orows = 64; ocols = 128; ldo = HID;
        size_t oo = (size_t)b * DIMC * HID + (size_t)nt * 128 * HID + h * 64;
        eoh = g_MThi + oo; eol = g_MTlo + oo;
    } else if (mode == MODE_S4) {
        int nt = bx & 1, mt = (bx >> 1) & 1, b = bx >> 2;
        size_t ao = (size_t)mt * 128 * HID;
        size_t bo = (size_t)b * DIMC * HID + (size_t)nt * 128 * HID;
        Ahp = g_WOh + ao; Alp = g_WOl + ao; Bhp = g_MThi + bo; Blp = g_MTlo + bo;
        lda = HID; ldb = HID; K = HID;
        ep = EP_F32R; ldo = DIMC;          // fp32 rna-rounded A for tf32 FINAL
        eo32 = g_A + (size_t)b * DIMC * DIMC + (size_t)mt * 128 * DIMC + nt * 128;
    } else {  // MODE_FINAL: tf32, A = g_A, B = XTr (both K-contig fp32)
        int mt = bx & 1, nt = (bx >> 1) & 31, b = bx >> 6;
        size_t ao = (size_t)b * DIMC * DIMC + (size_t)mt * 128 * DIMC;
        size_t bo = (size_t)b * NPIX * DIMC + (size_t)nt * 128 * DIMC;
        Af = g_A + ao; Bf = g_XTr + bo;
        tf32m = true;
        lda = DIMC; ldb = DIMC; K = DIMC;
        ep = EP_BIAS; ldo = NPIX;
        bias = b_out + mt * 128;
        eo32 = out + (size_t)b * DIMC * NPIX + (size_t)mt * 128 * NPIX + nt * 128;
    }

    const uint32_t sbase = smem_u32(sm);
    const int nch = K >> 5;

    // ---- loaders ----
    // bf16 KC tiles: 128 rows x 4 chunks of 8 bf16
    const int lrow = tid >> 2, lq = tid & 3;
    const int ra = lrow < Ar ? lrow : 0;
    const int rb = lrow < Br ? lrow : 0;
    const uint32_t doff = (uint32_t)(lrow * LROW + lq * 8) * 2;

    auto issue = [&](int c) {
        if (c < nch) {
            uint32_t stg = sbase + (uint32_t)(c & (NSTG - 1)) * STAGEB;
            int k0 = c * BK;
            if (tf32m) {
                // 128 rows x 8 chunks of 4 fp32; 1024 units over 512 threads x2
                #pragma unroll
                for (int i = 0; i < 2; ++i) {
                    int u = tid + i * 512;
                    int row = u >> 3, q = u & 7;
                    uint32_t d = stg + (uint32_t)(row * LROW4 + q * 4) * 4;
                    cp16(d,          Af + (size_t)row * lda + k0 + q * 4);
                    cp16(d + TILE4B, Bf + (size_t)row * ldb + k0 + q * 4);
                }
            } else {
                cp16(stg + doff,             Ahp + (size_t)ra * lda + k0 + lq * 8);
                cp16(stg + TILEB + doff,     Alp + (size_t)ra * lda + k0 + lq * 8);
                cp16(stg + 2 * TILEB + doff, Bhp + (size_t)rb * ldb + k0 + lq * 8);
                cp16(stg + 3 * TILEB + doff, Blp + (size_t)rb * ldb + k0 + lq * 8);
            }
        }
        CP_COMMIT();
    };

    float acc[2][4][4];
    #pragma unroll
    for (int a = 0; a < 2; ++a)
        #pragma unroll
        for (int b2 = 0; b2 < 4; ++b2)
            #pragma unroll
            for (int c = 0; c < 4; ++c) acc[a][b2][c] = 0.0f;

    // ---- fragment lane offsets ----
    // bf16 ldmatrix
    const uint32_t frow = (uint32_t)(lane & 15);
    const uint32_t fcol = (uint32_t)((lane >> 4) * 8);
    uint32_t aoff[2][2], boff[2][2];
    #pragma unroll
    for (int mi = 0; mi < 2; ++mi)
        #pragma unroll
        for (int s = 0; s < 2; ++s)
            aoff[mi][s] = (uint32_t)(((m0 + mi * 16 + frow) * LROW) + s * 16 + fcol) * 2;
    #pragma unroll
    for (int np = 0; np < 2; ++np)
        #pragma unroll
        for (int s = 0; s < 2; ++s)
            boff[np][s] = (uint32_t)(((n0 + np * 16 + frow) * LROW) + s * 16 + fcol) * 2;
    // tf32 ldmatrix (fp32-as-2xb16): lane group g = lane>>3, row r = lane&7
    const int lg = lane >> 3, lr = lane & 7;
    const uint32_t laneA4 = (uint32_t)((((lg & 1) * 8 + lr) * LROW4 + (lg >> 1) * 4) * 4);
    const uint32_t laneB4 = (uint32_t)((((lg >> 1) * 8 + lr) * LROW4 + (lg & 1) * 4) * 4);

    issue(0); issue(1); issue(2);

    for (int c = 0; c < nch; ++c) {
        CP_WAIT2();
        __syncthreads();
        issue(c + NSTG - 1);

        const uint32_t stg = sbase + (uint32_t)(c & (NSTG - 1)) * STAGEB;
        if (tf32m) {
            #pragma unroll
            for (int ks = 0; ks < 4; ++ks) {
                uint32_t a[2][4];
                #pragma unroll
                for (int mi = 0; mi < 2; ++mi)
                    LDSM4(a[mi][0], a[mi][1], a[mi][2], a[mi][3],
                          stg + (uint32_t)(((m0 + mi * 16) * LROW4 + ks * 8) * 4) + laneA4);
                #pragma unroll
                for (int np = 0; np < 2; ++np) {
                    uint32_t b0, b1, b2, b3;
                    LDSM4(b0, b1, b2, b3,
                          stg + TILE4B + (uint32_t)(((n0 + np * 16) * LROW4 + ks * 8) * 4) + laneB4);
                    #pragma unroll
                    for (int mi = 0; mi < 2; ++mi) {
                        mma1688t(acc[mi][2*np],   a[mi][0], a[mi][1], a[mi][2], a[mi][3], b0, b1);
                        mma1688t(acc[mi][2*np+1], a[mi][0], a[mi][1], a[mi][2], a[mi][3], b2, b3);
                    }
                }
            }
        } else {
            #pragma unroll
            for (int s = 0; s < 2; ++s) {
                uint32_t ah[2][4], al[2][4];
                #pragma unroll
                for (int mi = 0; mi < 2; ++mi) {
                    LDSM4(ah[mi][0], ah[mi][1], ah[mi][2], ah[mi][3], stg + aoff[mi][s]);
                    LDSM4(al[mi][0], al[mi][1], al[mi][2], al[mi][3], stg + TILEB + aoff[mi][s]);
                }
                #pragma unroll
                for (int np = 0; np < 2; ++np) {
                    uint32_t bh0e, bh0o, bh1e, bh1o, bl0e, bl0o, bl1e, bl1o;
                    LDSM4(bh0e, bh0o, bh1e, bh1o, stg + 2 * TILEB + boff[np][s]);
                    LDSM4(bl0e, bl0o, bl1e, bl1o, stg + 3 * TILEB + boff[np][s]);
                    #pragma unroll
                    for (int mi = 0; mi < 2; ++mi) {
                        mma16816(acc[mi][2*np],   ah[mi][0], ah[mi][1], ah[mi][2], ah[mi][3], bh0e, bh1e);
                        mma16816(acc[mi][2*np],   ah[mi][0], ah[mi][1], ah[mi][2], ah[mi][3], bl0e, bl1e);
                        mma16816(acc[mi][2*np],   al[mi][0], al[mi][1], al[mi][2], al[mi][3], bh0e, bh1e);
                        mma16816(acc[mi][2*np+1], ah[mi][0], ah[mi][1], ah[mi][2], ah[mi][3], bh0o, bh1o);
                        mma16816(acc[mi][2*np+1], ah[mi][0], ah[mi][1], ah[mi][2], ah[mi][3], bl0o, bl1o);
                        mma16816(acc[mi][2*np+1], al[mi][0], al[mi][1], al[mi][2], al[mi][3], bh0o, bh1o);
                    }
                }
            }
        }
    }

    // ---- epilogue ----
    const int gr = lane >> 2, gc = (lane & 3) * 2;
    #pragma unroll
    for (int mi = 0; mi < 2; ++mi) {
        #pragma unroll
        for (int ni = 0; ni < 4; ++ni) {
            int r = m0 + mi * 16 + gr;
            int c = n0 + ni * 8 + gc;
            if (r >= orows || c >= ocols) continue;
            float v0 = acc[mi][ni][0], v1 = acc[mi][ni][1];
            float v2 = acc[mi][ni][2], v3 = acc[mi][ni][3];
            if (ep == EP_BIAS) {
                float bl = bias[r], bh2 = bias[r + 8];
                v0 += bl; v1 += bl; v2 += bh2; v3 += bh2;
            }
            if (ep == EP_F32 || ep == EP_BIAS) {
                float2 p0 = {v0, v1}, p1 = {v2, v3};
                *(float2*)&eo32[(size_t)r * ldo + c] = p0;
                *(float2*)&eo32[(size_t)(r + 8) * ldo + c] = p1;
                if (em) {
                    em[(size_t)c * ldo + r] = v0;
                    em[(size_t)(c + 1) * ldo + r] = v1;
                    em[(size_t)c * ldo + r + 8] = v2;
                    em[(size_t)(c + 1) * ldo + r + 8] = v3;
                }
            } else if (ep == EP_F32R) {
                float2 p0 = {rna_tf32(v0), rna_tf32(v1)};
                float2 p1 = {rna_tf32(v2), rna_tf32(v3)};
                *(float2*)&eo32[(size_t)r * ldo + c] = p0;
                *(float2*)&eo32[(size_t)(r + 8) * ldo + c] = p1;
            } else if (ep == EP_HILO) {
                bf16 h0, l0, h1, l1, h2, l2, h3, l3;
                split2(v0, h0, l0); split2(v1, h1, l1);
                split2(v2, h2, l2); split2(v3, h3, l3);
                __nv_bfloat162 ph0 = {h0, h1}, pl0 = {l0, l1};
                __nv_bfloat162 ph1 = {h2, h3}, pl1 = {l2, l3};
                *(__nv_bfloat162*)&eoh[(size_t)r * ldo + c] = ph0;
                *(__nv_bfloat162*)&eol[(size_t)r * ldo + c] = pl0;
                *(__nv_bfloat162*)&eoh[(size_t)(r + 8) * ldo + c] = ph1;
                *(__nv_bfloat162*)&eol[(size_t)(r + 8) * ldo + c] = pl1;
            } else {   // EP_HILO_T : store transposed [col][row]
                bf16 h, l;
                split2(v0, h, l); eoh[(size_t)c * ldo + r] = h;       eol[(size_t)c * ldo + r] = l;
                split2(v1, h, l); eoh[(size_t)(c + 1) * ldo + r] = h; eol[(size_t)(c + 1) * ldo + r] = l;
                split2(v2, h, l); eoh[(size_t)c * ldo + r + 8] = h;   eol[(size_t)c * ldo + r + 8] = l;
                split2(v3, h, l); eoh[(size_t)(c + 1) * ldo + r + 8] = h; eol[(size_t)(c + 1) * ldo + r + 8] = l;
            }
        }
    }
}

// ---------------- launch ----------------
extern "C" void kernel_launch(void* const* d_in, const int* in_sizes, int n_in,
                              void* d_out, int out_size)
{
    const float* x     = (const float*)d_in[0];
    const float* w_qkv = (const float*)d_in[1];
    const float* w_out = (const float*)d_in[2];
    const float* b_out = (const float*)d_in[3];
    float* out = (float*)d_out;

    cudaFuncSetAttribute(mma_kernel, cudaFuncAttributeMaxDynamicSharedMemorySize, SMEMB);

    transform_x<<<dim3(128, 8, 16), dim3(32, 8)>>>(x);
    wsplit<<<1536, 256>>>(w_qkv, w_out);
    mma_kernel<<<3 * KS * 16, 512, SMEMB>>>(MODE_SYRK, b_out, out);
    reduce_g<<<1024, 256>>>();
    mma_kernel<<<128,  512, SMEMB>>>(MODE_S1,    b_out, out);
    mma_kernel<<<128,  512, SMEMB>>>(MODE_S2,    b_out, out);
    mma_kernel<<<256,  512, SMEMB>>>(MODE_S3,    b_out, out);
    mma_kernel<<<64,   512, SMEMB>>>(MODE_S4,    b_out, out);
    mma_kernel<<<1024, 512, SMEMB>>>(MODE_FINAL, b_out, out);
}

// round 11
// speedup vs baseline: 2.0693x; 1.1421x over previous
#include <cuda_runtime.h>
#include <cstdint>

#define DIMC 256
#define NPIX 4096
#define BATCH 16
#define HID 512
#define NH 8
#define DH 64
#define KS 8                  // SYRK split-K slices

#define BK 32
#define LROW4 36              // 32 + 4 pad fp32 (144B row)
#define TILE4B (128 * LROW4 * 4)    // 18432 B
#define STAGEB (2 * TILE4B)   // 36864 B
#define NSTG 4
#define SMEMB (NSTG * STAGEB) // 147456 B

// ---------------- scratch (device globals, all fp32 rna-rounded) ----------------
__device__ float g_Gp [KS * BATCH * DIMC * DIMC];
__device__ float g_Xr [BATCH * DIMC * NPIX];    // rna(x), [b][c][n]
__device__ float g_XTr[BATCH * NPIX * DIMC];    // rna(x) transposed, [b][n][c]
__device__ float g_Gr [BATCH * DIMC * DIMC];    // G (rna)
__device__ float g_Pr [BATCH * HID * DIMC];     // P = Wk@G (rna)
__device__ float g_CTr[BATCH * NH * DH * DH];   // C^T [bh][e][d] (rna)
__device__ float g_MTr[BATCH * DIMC * HID];     // M^T [b][c][j] (rna)
__device__ float g_A  [BATCH * DIMC * DIMC];    // A_b (rna)
__device__ float g_Wr [3 * HID * DIMC];         // rna(w_qkv)
__device__ float g_WOr[DIMC * HID];             // rna(w_out)
__device__ float g_WqTr[NH * DIMC * DH];        // rna(Wq^T / 8) [h][c][d]

// ---------------- helpers ----------------
__device__ __forceinline__ float rna_tf32(float v) {
    uint32_t r;
    asm("cvt.rna.tf32.f32 %0, %1;" : "=r"(r) : "f"(v));
    return __uint_as_float(r);
}
__device__ __forceinline__ uint32_t smem_u32(const void* p) {
    uint32_t a;
    asm("{ .reg .u64 t; cvta.to.shared.u64 t, %1; cvt.u32.u64 %0, t; }" : "=r"(a) : "l"(p));
    return a;
}
__device__ __forceinline__ void cp16(uint32_t dst, const void* src) {
    asm volatile("cp.async.cg.shared.global [%0], [%1], 16;" :: "r"(dst), "l"(src));
}
#define CP_COMMIT() asm volatile("cp.async.commit_group;" ::: "memory")
#define CP_WAIT2()  asm volatile("cp.async.wait_group 2;" ::: "memory")

#define LDSM4(r0, r1, r2, r3, a) \
    asm volatile("ldmatrix.sync.aligned.m8n8.x4.shared.b16 {%0,%1,%2,%3}, [%4];" \
                 : "=r"(r0), "=r"(r1), "=r"(r2), "=r"(r3) : "r"(a))

__device__ __forceinline__ void mma1688t(float c[4],
                                         uint32_t a0, uint32_t a1, uint32_t a2, uint32_t a3,
                                         uint32_t b0, uint32_t b1) {
    asm volatile(
        "mma.sync.aligned.m16n8k8.row.col.f32.tf32.tf32.f32 "
        "{%0,%1,%2,%3},{%4,%5,%6,%7},{%8,%9},{%0,%1,%2,%3};"
        : "+f"(c[0]), "+f"(c[1]), "+f"(c[2]), "+f"(c[3])
        : "r"(a0), "r"(a1), "r"(a2), "r"(a3), "r"(b0), "r"(b1));
}

// ---------------- transforms ----------------
// x fp32 -> rna-rounded Xr (same layout) + XTr (transposed)
__global__ void transform_x(const float* __restrict__ x) {
    __shared__ float tile[32][33];
    int b = blockIdx.z, c0 = blockIdx.y * 32, n0 = blockIdx.x * 32;
    int tx = threadIdx.x, ty = threadIdx.y;   // 32 x 8
    const float* xb = x + (size_t)b * DIMC * NPIX;
    #pragma unroll
    for (int i = 0; i < 4; ++i) {
        int c = c0 + ty + i * 8, n = n0 + tx;
        float r = rna_tf32(xb[(size_t)c * NPIX + n]);
        tile[ty + i * 8][tx] = r;
        g_Xr[(size_t)b * DIMC * NPIX + (size_t)c * NPIX + n] = r;
    }
    __syncthreads();
    #pragma unroll
    for (int i = 0; i < 4; ++i) {
        int n = n0 + ty + i * 8, c = c0 + tx;
        g_XTr[(size_t)b * NPIX * DIMC + (size_t)n * DIMC + c] = tile[tx][ty + i * 8];
    }
}

__global__ void wsplit(const float* __restrict__ w_qkv, const float* __restrict__ w_out) {
    int idx = blockIdx.x * 256 + threadIdx.x;
    if (idx < 3 * HID * DIMC) g_Wr[idx] = rna_tf32(w_qkv[idx]);
    if (idx < DIMC * HID)     g_WOr[idx] = rna_tf32(w_out[idx]);
    if (idx < NH * DIMC * DH) {
        int d = idx & 63, c = (idx >> 6) & 255, h = idx >> 14;
        g_WqTr[idx] = rna_tf32(0.125f * w_qkv[(size_t)(h * 64 + d) * DIMC + c]);
    }
}

__global__ void reduce_g() {
    int idx = blockIdx.x * 256 + threadIdx.x;          // 262144 float4s
    const size_t S4 = (size_t)BATCH * DIMC * DIMC / 4;
    const float4* p = (const float4*)g_Gp;
    float4 v = p[idx];
    #pragma unroll
    for (int s = 1; s < KS; ++s) {
        float4 t = p[idx + s * S4];
        v.x += t.x; v.y += t.y; v.z += t.z; v.w += t.w;
    }
    float4 r = {rna_tf32(v.x), rna_tf32(v.y), rna_tf32(v.z), rna_tf32(v.w)};
    ((float4*)g_Gr)[idx] = r;
}

// ---------------- modes ----------------
#define MODE_SYRK  0
#define MODE_S1    1
#define MODE_S2    2
#define MODE_S3    3
#define MODE_S4    4
#define MODE_FINAL 5

#define EP_F32    0
#define EP_BIAS   1
#define EP_F32R   2
#define EP_F32R_T 3

__global__ void __launch_bounds__(512)
mma_kernel(int mode, const float* __restrict__ b_out, float* __restrict__ out)
{
    extern __shared__ char sm[];
    const int tid = threadIdx.x;
    const int lane = tid & 31, wid = tid >> 5;
    const int m0 = (wid >> 2) * 32, n0 = (wid & 3) * 32;   // 4x4 warps, 32x32 tiles
    const int bx = blockIdx.x;

    // ---- decode job ----
    const float *Af, *Bf;
    int lda, ldb, K, Ar = 128, Br = 128;
    int ep, orows = 128, ocols = 128, ldo;
    const float* bias = nullptr;
    float* eo32 = nullptr;
    float* em = nullptr;

    if (mode == MODE_SYRK) {
        int p = bx % 3, ks = (bx / 3) & (KS - 1), b = bx / (3 * KS);
        int ti = (p == 2) ? 1 : 0;
        int tj = (p == 0) ? 0 : 1;
        size_t ao = ((size_t)b * DIMC + ti * 128) * NPIX + (size_t)ks * (NPIX / KS);
        size_t bo = ((size_t)b * DIMC + tj * 128) * NPIX + (size_t)ks * (NPIX / KS);
        Af = g_Xr + ao; Bf = g_Xr + bo;
        lda = NPIX; ldb = NPIX; K = NPIX / KS;
        ep = EP_F32; ldo = DIMC;
        float* Gp = g_Gp + ((size_t)ks * BATCH + b) * DIMC * DIMC;
        eo32 = Gp + (size_t)ti * 128 * DIMC + tj * 128;
        if (ti != tj) em = Gp + (size_t)tj * 128 * DIMC + ti * 128;
    } else if (mode == MODE_S1) {
        int mt = bx & 3, nt = (bx >> 2) & 1, b = bx >> 3;
        Af = g_Wr + (size_t)(HID + mt * 128) * DIMC;                 // Wk rows
        Bf = g_Gr + (size_t)b * DIMC * DIMC + (size_t)nt * 128 * DIMC;  // G symmetric
        lda = DIMC; ldb = DIMC; K = DIMC;
        ep = EP_F32R; ldo = DIMC;
        eo32 = g_Pr + (size_t)b * HID * DIMC + (size_t)mt * 128 * DIMC + nt * 128;
    } else if (mode == MODE_S2) {
        int h = bx & 7, b = bx >> 3;
        Af = g_Pr + (size_t)b * HID * DIMC + (size_t)h * 64 * DIMC;
        Bf = g_Wr + (size_t)(2 * HID + h * 64) * DIMC;               // Wv rows
        lda = DIMC; ldb = DIMC; K = DIMC; Ar = 64; Br = 64;
        ep = EP_F32R_T; orows = 64; ocols = 64; ldo = 64;
        eo32 = g_CTr + (size_t)bx * DH * DH;                          // CT[e][d]
    } else if (mode == MODE_S3) {
        int nt = bx & 1, bh = bx >> 1, h = bh & 7, b = bh >> 3;
        Af = g_CTr + (size_t)bh * DH * DH;                            // CT[e][d] K-contig
        Bf = g_WqTr + (size_t)h * DIMC * DH + (size_t)nt * 128 * DH;  // WqT[c][d]
        lda = DH; ldb = DH; K = DH; Ar = 64; Br = 128;
        ep = EP_F32R_T; orows = 64; ocols = 128; ldo = HID;
        eo32 = g_MTr + (size_t)b * DIMC * HID + (size_t)nt * 128 * HID + h * 64;
    } else if (mode == MODE_S4) {
        int nt = bx & 1, mt = (bx >> 1) & 1, b = bx >> 2;
        Af = g_WOr + (size_t)mt * 128 * HID;
        Bf = g_MTr + (size_t)b * DIMC * HID + (size_t)nt * 128 * HID; // MT[c][j]
        lda = HID; ldb = HID; K = HID;
        ep = EP_F32R; ldo = DIMC;
        eo32 = g_A + (size_t)b * DIMC * DIMC + (size_t)mt * 128 * DIMC + nt * 128;
    } else {  // MODE_FINAL
        int mt = bx & 1, nt = (bx >> 1) & 31, b = bx >> 6;
        Af = g_A + (size_t)b * DIMC * DIMC + (size_t)mt * 128 * DIMC;
        Bf = g_XTr + (size_t)b * NPIX * DIMC + (size_t)nt * 128 * DIMC;
        lda = DIMC; ldb = DIMC; K = DIMC;
        ep = EP_BIAS; ldo = NPIX;
        bias = b_out + mt * 128;
        eo32 = out + (size_t)b * DIMC * NPIX + (size_t)mt * 128 * NPIX + nt * 128;
    }

    const uint32_t sbase = smem_u32(sm);
    const int nch = K >> 5;

    auto issue = [&](int c) {
        if (c < nch) {
            uint32_t stg = sbase + (uint32_t)(c & (NSTG - 1)) * STAGEB;
            int k0 = c * BK;
            #pragma unroll
            for (int i = 0; i < 2; ++i) {
                int u = tid + i * 512;
                int row = u >> 3, q = u & 7;
                int ra = row < Ar ? row : 0;
                int rb = row < Br ? row : 0;
                uint32_t d = stg + (uint32_t)(row * LROW4 + q * 4) * 4;
                cp16(d,          Af + (size_t)ra * lda + k0 + q * 4);
                cp16(d + TILE4B, Bf + (size_t)rb * ldb + k0 + q * 4);
            }
        }
        CP_COMMIT();
    };

    float acc[2][4][4];
    #pragma unroll
    for (int a = 0; a < 2; ++a)
        #pragma unroll
        for (int b2 = 0; b2 < 4; ++b2)
            #pragma unroll
            for (int c = 0; c < 4; ++c) acc[a][b2][c] = 0.0f;

    // tf32 fragment loads via b16 ldmatrix: lane group g = lane>>3, row r = lane&7
    const int lg = lane >> 3, lr = lane & 7;
    const uint32_t laneA4 = (uint32_t)((((lg & 1) * 8 + lr) * LROW4 + (lg >> 1) * 4) * 4);
    const uint32_t laneB4 = (uint32_t)((((lg >> 1) * 8 + lr) * LROW4 + (lg & 1) * 4) * 4);

    issue(0); issue(1); issue(2);

    for (int c = 0; c < nch; ++c) {
        CP_WAIT2();
        __syncthreads();
        issue(c + NSTG - 1);

        const uint32_t stg = sbase + (uint32_t)(c & (NSTG - 1)) * STAGEB;
        #pragma unroll
        for (int ks = 0; ks < 4; ++ks) {
            uint32_t a[2][4];
            #pragma unroll
            for (int mi = 0; mi < 2; ++mi)
                LDSM4(a[mi][0], a[mi][1], a[mi][2], a[mi][3],
                      stg + (uint32_t)(((m0 + mi * 16) * LROW4 + ks * 8) * 4) + laneA4);
            #pragma unroll
            for (int np = 0; np < 2; ++np) {
                uint32_t b0, b1, b2, b3;
                LDSM4(b0, b1, b2, b3,
                      stg + TILE4B + (uint32_t)(((n0 + np * 16) * LROW4 + ks * 8) * 4) + laneB4);
                #pragma unroll
                for (int mi = 0; mi < 2; ++mi) {
                    mma1688t(acc[mi][2*np],   a[mi][0], a[mi][1], a[mi][2], a[mi][3], b0, b1);
                    mma1688t(acc[mi][2*np+1], a[mi][0], a[mi][1], a[mi][2], a[mi][3], b2, b3);
                }
            }
        }
    }

    // ---- epilogue ----
    const int gr = lane >> 2, gc = (lane & 3) * 2;
    #pragma unroll
    for (int mi = 0; mi < 2; ++mi) {
        #pragma unroll
        for (int ni = 0; ni < 4; ++ni) {
            int r = m0 + mi * 16 + gr;
            int c = n0 + ni * 8 + gc;
            if (r >= orows || c >= ocols) continue;
            float v0 = acc[mi][ni][0], v1 = acc[mi][ni][1];
            float v2 = acc[mi][ni][2], v3 = acc[mi][ni][3];
            if (ep == EP_BIAS) {
                float bl = bias[r], bh = bias[r + 8];
                v0 += bl; v1 += bl; v2 += bh; v3 += bh;
            }
            if (ep == EP_F32 || ep == EP_BIAS) {
                float2 p0 = {v0, v1}, p1 = {v2, v3};
                *(float2*)&eo32[(size_t)r * ldo + c] = p0;
                *(float2*)&eo32[(size_t)(r + 8) * ldo + c] = p1;
                if (em) {
                    em[(size_t)c * ldo + r] = v0;
                    em[(size_t)(c + 1) * ldo + r] = v1;
                    em[(size_t)c * ldo + r + 8] = v2;
                    em[(size_t)(c + 1) * ldo + r + 8] = v3;
                }
            } else if (ep == EP_F32R) {
                float2 p0 = {rna_tf32(v0), rna_tf32(v1)};
                float2 p1 = {rna_tf32(v2), rna_tf32(v3)};
                *(float2*)&eo32[(size_t)r * ldo + c] = p0;
                *(float2*)&eo32[(size_t)(r + 8) * ldo + c] = p1;
            } else {   // EP_F32R_T : rna + transposed store [col][row]
                eo32[(size_t)c * ldo + r]           = rna_tf32(v0);
                eo32[(size_t)(c + 1) * ldo + r]     = rna_tf32(v1);
                eo32[(size_t)c * ldo + r + 8]       = rna_tf32(v2);
                eo32[(size_t)(c + 1) * ldo + r + 8] = rna_tf32(v3);
            }
        }
    }
}

// ---------------- launch ----------------
extern "C" void kernel_launch(void* const* d_in, const int* in_sizes, int n_in,
                              void* d_out, int out_size)
{
    const float* x     = (const float*)d_in[0];
    const float* w_qkv = (const float*)d_in[1];
    const float* w_out = (const float*)d_in[2];
    const float* b_out = (const float*)d_in[3];
    float* out = (float*)d_out;

    cudaFuncSetAttribute(mma_kernel, cudaFuncAttributeMaxDynamicSharedMemorySize, SMEMB);

    transform_x<<<dim3(128, 8, 16), dim3(32, 8)>>>(x);
    wsplit<<<1536, 256>>>(w_qkv, w_out);
    mma_kernel<<<3 * KS * 16, 512, SMEMB>>>(MODE_SYRK, b_out, out);
    reduce_g<<<1024, 256>>>();
    mma_kernel<<<128,  512, SMEMB>>>(MODE_S1,    b_out, out);
    mma_kernel<<<128,  512, SMEMB>>>(MODE_S2,    b_out, out);
    mma_kernel<<<256,  512, SMEMB>>>(MODE_S3,    b_out, out);
    mma_kernel<<<64,   512, SMEMB>>>(MODE_S4,    b_out, out);
    mma_kernel<<<1024, 512, SMEMB>>>(MODE_FINAL, b_out, out);
}

// round 12
// speedup vs baseline: 2.0707x; 1.0007x over previous
#include <cuda_runtime.h>
#include <cstdint>

#define DIMC 256
#define NPIX 4096
#define BATCH 16
#define HID 512
#define NH 8
#define DH 64
#define KS 8                  // SYRK split-K slices

#define BK 32
#define LROW4 36              // 32 + 4 pad fp32 (144B row)
#define TILE4B (128 * LROW4 * 4)    // 18432 B
#define STAGEB (2 * TILE4B)   // 36864 B
#define NSTG 4
#define SMEMB (NSTG * STAGEB) // 147456 B

// ---------------- scratch (device globals, all fp32 rna-rounded) ----------------
__device__ float g_Gp [KS * BATCH * DIMC * DIMC];
__device__ float g_Xr [BATCH * DIMC * NPIX];    // rna(x), [b][c][n]
__device__ float g_XTr[BATCH * NPIX * DIMC];    // rna(x) transposed, [b][n][c]
__device__ float g_Gr [BATCH * DIMC * DIMC];    // G (rna)
__device__ float g_Pr [BATCH * HID * DIMC];     // P = Wk@G (rna)
__device__ float g_CTr[BATCH * NH * DH * DH];   // C^T [bh][e][d] (rna)
__device__ float g_MTr[BATCH * DIMC * HID];     // M^T [b][c][j] (rna)
__device__ float g_A  [BATCH * DIMC * DIMC];    // A_b (rna)
__device__ float g_Wr [3 * HID * DIMC];         // rna(w_qkv)
__device__ float g_WOr[DIMC * HID];             // rna(w_out)
__device__ float g_WqTr[NH * DIMC * DH];        // rna(Wq^T / 8) [h][c][d]

// ---------------- helpers ----------------
__device__ __forceinline__ float rna_tf32(float v) {
    uint32_t r;
    asm("cvt.rna.tf32.f32 %0, %1;" : "=r"(r) : "f"(v));
    return __uint_as_float(r);
}
__device__ __forceinline__ uint32_t smem_u32(const void* p) {
    uint32_t a;
    asm("{ .reg .u64 t; cvta.to.shared.u64 t, %1; cvt.u32.u64 %0, t; }" : "=r"(a) : "l"(p));
    return a;
}
__device__ __forceinline__ void cp16(uint32_t dst, const void* src) {
    asm volatile("cp.async.cg.shared.global [%0], [%1], 16;" :: "r"(dst), "l"(src));
}
#define CP_COMMIT() asm volatile("cp.async.commit_group;" ::: "memory")
#define CP_WAIT2()  asm volatile("cp.async.wait_group 2;" ::: "memory")

#define LDSM4(r0, r1, r2, r3, a) \
    asm volatile("ldmatrix.sync.aligned.m8n8.x4.shared.b16 {%0,%1,%2,%3}, [%4];" \
                 : "=r"(r0), "=r"(r1), "=r"(r2), "=r"(r3) : "r"(a))

__device__ __forceinline__ void mma1688t(float c[4],
                                         uint32_t a0, uint32_t a1, uint32_t a2, uint32_t a3,
                                         uint32_t b0, uint32_t b1) {
    asm volatile(
        "mma.sync.aligned.m16n8k8.row.col.f32.tf32.tf32.f32 "
        "{%0,%1,%2,%3},{%4,%5,%6,%7},{%8,%9},{%0,%1,%2,%3};"
        : "+f"(c[0]), "+f"(c[1]), "+f"(c[2]), "+f"(c[3])
        : "r"(a0), "r"(a1), "r"(a2), "r"(a3), "r"(b0), "r"(b1));
}

// ---------------- transforms ----------------
// x fp32 -> rna-rounded Xr (same layout) + XTr (transposed)
__global__ void transform_x(const float* __restrict__ x) {
    __shared__ float tile[32][33];
    int b = blockIdx.z, c0 = blockIdx.y * 32, n0 = blockIdx.x * 32;
    int tx = threadIdx.x, ty = threadIdx.y;   // 32 x 8
    const float* xb = x + (size_t)b * DIMC * NPIX;
    #pragma unroll
    for (int i = 0; i < 4; ++i) {
        int c = c0 + ty + i * 8, n = n0 + tx;
        float r = rna_tf32(xb[(size_t)c * NPIX + n]);
        tile[ty + i * 8][tx] = r;
        g_Xr[(size_t)b * DIMC * NPIX + (size_t)c * NPIX + n] = r;
    }
    __syncthreads();
    #pragma unroll
    for (int i = 0; i < 4; ++i) {
        int n = n0 + ty + i * 8, c = c0 + tx;
        g_XTr[(size_t)b * NPIX * DIMC + (size_t)n * DIMC + c] = tile[tx][ty + i * 8];
    }
}

__global__ void wsplit(const float* __restrict__ w_qkv, const float* __restrict__ w_out) {
    int idx = blockIdx.x * 256 + threadIdx.x;
    if (idx < 3 * HID * DIMC) g_Wr[idx] = rna_tf32(w_qkv[idx]);
    if (idx < DIMC * HID)     g_WOr[idx] = rna_tf32(w_out[idx]);
    if (idx < NH * DIMC * DH) {
        int d = idx & 63, c = (idx >> 6) & 255, h = idx >> 14;
        g_WqTr[idx] = rna_tf32(0.125f * w_qkv[(size_t)(h * 64 + d) * DIMC + c]);
    }
}

__global__ void reduce_g() {
    int idx = blockIdx.x * 256 + threadIdx.x;          // 262144 float4s
    const size_t S4 = (size_t)BATCH * DIMC * DIMC / 4;
    const float4* p = (const float4*)g_Gp;
    float4 v = p[idx];
    #pragma unroll
    for (int s = 1; s < KS; ++s) {
        float4 t = p[idx + s * S4];
        v.x += t.x; v.y += t.y; v.z += t.z; v.w += t.w;
    }
    float4 r = {rna_tf32(v.x), rna_tf32(v.y), rna_tf32(v.z), rna_tf32(v.w)};
    ((float4*)g_Gr)[idx] = r;
}

// ---------------- modes ----------------
#define MODE_SYRK  0
#define MODE_S1    1
#define MODE_S2    2
#define MODE_S3    3
#define MODE_S4    4
#define MODE_FINAL 5

#define EP_F32    0
#define EP_BIAS   1
#define EP_F32R   2
#define EP_F32R_T 3

__global__ void __launch_bounds__(512)
mma_kernel(int mode, const float* __restrict__ b_out, float* __restrict__ out)
{
    extern __shared__ char sm[];
    const int tid = threadIdx.x;
    const int lane = tid & 31, wid = tid >> 5;
    const int m0 = (wid >> 2) * 32, n0 = (wid & 3) * 32;   // 4x4 warps, 32x32 tiles
    const int bx = blockIdx.x;

    // ---- decode job ----
    const float *Af, *Bf;
    int lda, ldb, K, Ar = 128, Br = 128;
    int ep, orows = 128, ocols = 128, ldo;
    const float* bias = nullptr;
    float* eo32 = nullptr;
    float* em = nullptr;

    if (mode == MODE_SYRK) {
        int p = bx % 3, ks = (bx / 3) & (KS - 1), b = bx / (3 * KS);
        int ti = (p == 2) ? 1 : 0;
        int tj = (p == 0) ? 0 : 1;
        size_t ao = ((size_t)b * DIMC + ti * 128) * NPIX + (size_t)ks * (NPIX / KS);
        size_t bo = ((size_t)b * DIMC + tj * 128) * NPIX + (size_t)ks * (NPIX / KS);
        Af = g_Xr + ao; Bf = g_Xr + bo;
        lda = NPIX; ldb = NPIX; K = NPIX / KS;
        ep = EP_F32; ldo = DIMC;
        float* Gp = g_Gp + ((size_t)ks * BATCH + b) * DIMC * DIMC;
        eo32 = Gp + (size_t)ti * 128 * DIMC + tj * 128;
        if (ti != tj) em = Gp + (size_t)tj * 128 * DIMC + ti * 128;
    } else if (mode == MODE_S1) {
        int mt = bx & 3, nt = (bx >> 2) & 1, b = bx >> 3;
        Af = g_Wr + (size_t)(HID + mt * 128) * DIMC;                 // Wk rows
        Bf = g_Gr + (size_t)b * DIMC * DIMC + (size_t)nt * 128 * DIMC;  // G symmetric
        lda = DIMC; ldb = DIMC; K = DIMC;
        ep = EP_F32R; ldo = DIMC;
        eo32 = g_Pr + (size_t)b * HID * DIMC + (size_t)mt * 128 * DIMC + nt * 128;
    } else if (mode == MODE_S2) {
        int h = bx & 7, b = bx >> 3;
        Af = g_Pr + (size_t)b * HID * DIMC + (size_t)h * 64 * DIMC;
        Bf = g_Wr + (size_t)(2 * HID + h * 64) * DIMC;               // Wv rows
        lda = DIMC; ldb = DIMC; K = DIMC; Ar = 64; Br = 64;
        ep = EP_F32R_T; orows = 64; ocols = 64; ldo = 64;
        eo32 = g_CTr + (size_t)bx * DH * DH;                          // CT[e][d]
    } else if (mode == MODE_S3) {
        int nt = bx & 1, bh = bx >> 1, h = bh & 7, b = bh >> 3;
        Af = g_CTr + (size_t)bh * DH * DH;                            // CT[e][d] K-contig
        Bf = g_WqTr + (size_t)h * DIMC * DH + (size_t)nt * 128 * DH;  // WqT[c][d]
        lda = DH; ldb = DH; K = DH; Ar = 64; Br = 128;
        ep = EP_F32R_T; orows = 64; ocols = 128; ldo = HID;
        eo32 = g_MTr + (size_t)b * DIMC * HID + (size_t)nt * 128 * HID + h * 64;
    } else if (mode == MODE_S4) {
        int nt = bx & 1, mt = (bx >> 1) & 1, b = bx >> 2;
        Af = g_WOr + (size_t)mt * 128 * HID;
        Bf = g_MTr + (size_t)b * DIMC * HID + (size_t)nt * 128 * HID; // MT[c][j]
        lda = HID; ldb = HID; K = HID;
        ep = EP_F32R; ldo = DIMC;
        eo32 = g_A + (size_t)b * DIMC * DIMC + (size_t)mt * 128 * DIMC + nt * 128;
    } else {  // MODE_FINAL
        int mt = bx & 1, nt = (bx >> 1) & 31, b = bx >> 6;
        Af = g_A + (size_t)b * DIMC * DIMC + (size_t)mt * 128 * DIMC;
        Bf = g_XTr + (size_t)b * NPIX * DIMC + (size_t)nt * 128 * DIMC;
        lda = DIMC; ldb = DIMC; K = DIMC;
        ep = EP_BIAS; ldo = NPIX;
        bias = b_out + mt * 128;
        eo32 = out + (size_t)b * DIMC * NPIX + (size_t)mt * 128 * NPIX + nt * 128;
    }

    const uint32_t sbase = smem_u32(sm);
    const int nch = K >> 5;

    auto issue = [&](int c) {
        if (c < nch) {
            uint32_t stg = sbase + (uint32_t)(c & (NSTG - 1)) * STAGEB;
            int k0 = c * BK;
            #pragma unroll
            for (int i = 0; i < 2; ++i) {
                int u = tid + i * 512;
                int row = u >> 3, q = u & 7;
                int ra = row < Ar ? row : 0;
                int rb = row < Br ? row : 0;
                uint32_t d = stg + (uint32_t)(row * LROW4 + q * 4) * 4;
                cp16(d,          Af + (size_t)ra * lda + k0 + q * 4);
                cp16(d + TILE4B, Bf + (size_t)rb * ldb + k0 + q * 4);
            }
        }
        CP_COMMIT();
    };

    float acc[2][4][4];
    #pragma unroll
    for (int a = 0; a < 2; ++a)
        #pragma unroll
        for (int b2 = 0; b2 < 4; ++b2)
            #pragma unroll
            for (int c = 0; c < 4; ++c) acc[a][b2][c] = 0.0f;

    // tf32 fragment loads via b16 ldmatrix: lane group g = lane>>3, row r = lane&7
    const int lg = lane >> 3, lr = lane & 7;
    const uint32_t laneA4 = (uint32_t)((((lg & 1) * 8 + lr) * LROW4 + (lg >> 1) * 4) * 4);
    const uint32_t laneB4 = (uint32_t)((((lg >> 1) * 8 + lr) * LROW4 + (lg & 1) * 4) * 4);

    issue(0); issue(1); issue(2);

    for (int c = 0; c < nch; ++c) {
        CP_WAIT2();
        __syncthreads();
        issue(c + NSTG - 1);

        const uint32_t stg = sbase + (uint32_t)(c & (NSTG - 1)) * STAGEB;
        #pragma unroll
        for (int ks = 0; ks < 4; ++ks) {
            uint32_t a[2][4];
            #pragma unroll
            for (int mi = 0; mi < 2; ++mi)
                LDSM4(a[mi][0], a[mi][1], a[mi][2], a[mi][3],
                      stg + (uint32_t)(((m0 + mi * 16) * LROW4 + ks * 8) * 4) + laneA4);
            #pragma unroll
            for (int np = 0; np < 2; ++np) {
                uint32_t b0, b1, b2, b3;
                LDSM4(b0, b1, b2, b3,
                      stg + TILE4B + (uint32_t)(((n0 + np * 16) * LROW4 + ks * 8) * 4) + laneB4);
                #pragma unroll
                for (int mi = 0; mi < 2; ++mi) {
                    mma1688t(acc[mi][2*np],   a[mi][0], a[mi][1], a[mi][2], a[mi][3], b0, b1);
                    mma1688t(acc[mi][2*np+1], a[mi][0], a[mi][1], a[mi][2], a[mi][3], b2, b3);
                }
            }
        }
    }

    // ---- epilogue ----
    const int gr = lane >> 2, gc = (lane & 3) * 2;
    #pragma unroll
    for (int mi = 0; mi < 2; ++mi) {
        #pragma unroll
        for (int ni = 0; ni < 4; ++ni) {
            int r = m0 + mi * 16 + gr;
            int c = n0 + ni * 8 + gc;
            if (r >= orows || c >= ocols) continue;
            float v0 = acc[mi][ni][0], v1 = acc[mi][ni][1];
            float v2 = acc[mi][ni][2], v3 = acc[mi][ni][3];
            if (ep == EP_BIAS) {
                float bl = bias[r], bh = bias[r + 8];
                v0 += bl; v1 += bl; v2 += bh; v3 += bh;
            }
            if (ep == EP_F32 || ep == EP_BIAS) {
                float2 p0 = {v0, v1}, p1 = {v2, v3};
                *(float2*)&eo32[(size_t)r * ldo + c] = p0;
                *(float2*)&eo32[(size_t)(r + 8) * ldo + c] = p1;
                if (em) {
                    em[(size_t)c * ldo + r] = v0;
                    em[(size_t)(c + 1) * ldo + r] = v1;
                    em[(size_t)c * ldo + r + 8] = v2;
                    em[(size_t)(c + 1) * ldo + r + 8] = v3;
                }
            } else if (ep == EP_F32R) {
                float2 p0 = {rna_tf32(v0), rna_tf32(v1)};
                float2 p1 = {rna_tf32(v2), rna_tf32(v3)};
                *(float2*)&eo32[(size_t)r * ldo + c] = p0;
                *(float2*)&eo32[(size_t)(r + 8) * ldo + c] = p1;
            } else {   // EP_F32R_T : rna + transposed store [col][row]
                eo32[(size_t)c * ldo + r]           = rna_tf32(v0);
                eo32[(size_t)(c + 1) * ldo + r]     = rna_tf32(v1);
                eo32[(size_t)c * ldo + r + 8]       = rna_tf32(v2);
                eo32[(size_t)(c + 1) * ldo + r + 8] = rna_tf32(v3);
            }
        }
    }
}

// ---------------- launch ----------------
extern "C" void kernel_launch(void* const* d_in, const int* in_sizes, int n_in,
                              void* d_out, int out_size)
{
    const float* x     = (const float*)d_in[0];
    const float* w_qkv = (const float*)d_in[1];
    const float* w_out = (const float*)d_in[2];
    const float* b_out = (const float*)d_in[3];
    float* out = (float*)d_out;

    cudaFuncSetAttribute(mma_kernel, cudaFuncAttributeMaxDynamicSharedMemorySize, SMEMB);

    transform_x<<<dim3(128, 8, 16), dim3(32, 8)>>>(x);
    wsplit<<<1536, 256>>>(w_qkv, w_out);
    mma_kernel<<<3 * KS * 16, 512, SMEMB>>>(MODE_SYRK, b_out, out);
    reduce_g<<<1024, 256>>>();
    mma_kernel<<<128,  512, SMEMB>>>(MODE_S1,    b_out, out);
    mma_kernel<<<128,  512, SMEMB>>>(MODE_S2,    b_out, out);
    mma_kernel<<<256,  512, SMEMB>>>(MODE_S3,    b_out, out);
    mma_kernel<<<64,   512, SMEMB>>>(MODE_S4,    b_out, out);
    mma_kernel<<<1024, 512, SMEMB>>>(MODE_FINAL, b_out, out);
}